// round 1
// baseline (speedup 1.0000x reference)
#include <cuda_runtime.h>
#include <math.h>

#define B_   2
#define T_   4096
#define C_   768
#define NH_  12
#define HD_  64
#define C3_  (3*C_)

// Scratch (allocation-free: __device__ globals)
__device__ float g_qkv[(size_t)B_*T_*C3_];   // 75.5 MB
__device__ float g_y[(size_t)B_*T_*C_];      // 25.2 MB

// ---------------------------------------------------------------------------
// Classic 128x128x8 SGEMM with bias: C[m][n] = sum_k A[m][k]*B[k][n] + bias[n]
// 256 threads, 8x8 per thread, float4 global/shared traffic.
// ---------------------------------------------------------------------------
__global__ __launch_bounds__(256) void sgemm_bias_kernel(
    const float* __restrict__ A, const float* __restrict__ Bm,
    const float* __restrict__ bias, float* __restrict__ Cm,
    int M, int N, int K)
{
    __shared__ float As[8][128];   // transposed A tile
    __shared__ float Bs[8][128];

    const int tid = threadIdx.x;
    const int m0 = blockIdx.y * 128;
    const int n0 = blockIdx.x * 128;
    const int tx = tid & 15, ty = tid >> 4;
    const int row0 = ty * 8, col0 = tx * 8;

    float acc[8][8];
    #pragma unroll
    for (int i = 0; i < 8; i++)
        #pragma unroll
        for (int j = 0; j < 8; j++) acc[i][j] = 0.f;

    const int aRow = tid >> 1, aCol = (tid & 1) * 4;
    const int bRow = tid >> 5, bCol = (tid & 31) * 4;

    for (int k0 = 0; k0 < K; k0 += 8) {
        float4 av = *reinterpret_cast<const float4*>(
            &A[(size_t)(m0 + aRow) * K + k0 + aCol]);
        float4 bv = *reinterpret_cast<const float4*>(
            &Bm[(size_t)(k0 + bRow) * N + n0 + bCol]);
        __syncthreads();   // protect previous iteration's reads
        As[aCol + 0][aRow] = av.x;
        As[aCol + 1][aRow] = av.y;
        As[aCol + 2][aRow] = av.z;
        As[aCol + 3][aRow] = av.w;
        *reinterpret_cast<float4*>(&Bs[bRow][bCol]) = bv;
        __syncthreads();
        #pragma unroll
        for (int kk = 0; kk < 8; kk++) {
            float a[8], b[8];
            #pragma unroll
            for (int i = 0; i < 8; i++) a[i] = As[kk][row0 + i];
            #pragma unroll
            for (int j = 0; j < 8; j++) b[j] = Bs[kk][col0 + j];
            #pragma unroll
            for (int i = 0; i < 8; i++)
                #pragma unroll
                for (int j = 0; j < 8; j++)
                    acc[i][j] += a[i] * b[j];
        }
    }

    #pragma unroll
    for (int i = 0; i < 8; i++) {
        #pragma unroll
        for (int j = 0; j < 8; j += 4) {
            float4 o;
            o.x = acc[i][j + 0] + bias[n0 + col0 + j + 0];
            o.y = acc[i][j + 1] + bias[n0 + col0 + j + 1];
            o.z = acc[i][j + 2] + bias[n0 + col0 + j + 2];
            o.w = acc[i][j + 3] + bias[n0 + col0 + j + 3];
            *reinterpret_cast<float4*>(
                &Cm[(size_t)(m0 + row0 + i) * N + n0 + col0 + j]) = o;
        }
    }
}

// ---------------------------------------------------------------------------
// Flash attention, fp32. One block = one (b, h, 64-query tile).
// Tiles: Qs 64x64, Ks 64x64 (reused as P after S is computed), Vs 64x64.
// Online softmax with per-row stats in smem; O (64x64) in registers 4x4/thread.
// Causal: k-tile loop only runs kt <= bx; masking only on the diagonal tile.
// ---------------------------------------------------------------------------
#define FL_SMEM_FLOATS (3*4096 + 1024 + 3*64)
#define FL_SMEM_BYTES  (FL_SMEM_FLOATS * 4)

__global__ __launch_bounds__(256) void flash_kernel()
{
    extern __shared__ float smem[];
    float* Qs  = smem;                 // 64*64
    float* Ks  = Qs + 4096;            // 64*64, reused as P
    float* Vs  = Ks + 4096;            // 64*64
    float* red = Vs + 4096;            // 64*16
    float* m_s = red + 1024;           // 64
    float* l_s = m_s + 64;             // 64
    float* a_s = l_s + 64;             // 64 (alpha)

    const int tid = threadIdx.x;
    const int bx = blockIdx.x;         // query tile
    const int h  = blockIdx.y;
    const int b  = blockIdx.z;
    const int q0 = bx * 64;

    const int tx = tid & 15, ty = tid >> 4;
    const int r0 = ty * 4, c0 = tx * 4;

    // Load Q tile, pre-scaled by 1/sqrt(HD)
    {
        const int lr = tid >> 4;
        const int lc = (tid & 15) * 4;
        #pragma unroll
        for (int it = 0; it < 4; it++) {
            int rr = lr + it * 16;
            float4 v = *reinterpret_cast<const float4*>(
                &g_qkv[((size_t)(b * T_ + q0 + rr)) * C3_ + h * HD_ + lc]);
            v.x *= 0.125f; v.y *= 0.125f; v.z *= 0.125f; v.w *= 0.125f;
            *reinterpret_cast<float4*>(&Qs[rr * 64 + lc]) = v;
        }
    }
    if (tid < 64) { m_s[tid] = -INFINITY; l_s[tid] = 0.f; }

    float4 o4[4];
    #pragma unroll
    for (int i = 0; i < 4; i++) o4[i] = make_float4(0.f, 0.f, 0.f, 0.f);

    for (int kt = 0; kt <= bx; kt++) {
        __syncthreads();  // previous iteration's P/V reads done before overwrite
        // Load K,V tiles
        {
            const int lr = tid >> 4;
            const int lc = (tid & 15) * 4;
            #pragma unroll
            for (int it = 0; it < 4; it++) {
                int rr = lr + it * 16;
                size_t base = ((size_t)(b * T_ + kt * 64 + rr)) * C3_ + h * HD_ + lc;
                *reinterpret_cast<float4*>(&Ks[rr * 64 + lc]) =
                    *reinterpret_cast<const float4*>(&g_qkv[C_ + base]);
                *reinterpret_cast<float4*>(&Vs[rr * 64 + lc]) =
                    *reinterpret_cast<const float4*>(&g_qkv[2 * C_ + base]);
            }
        }
        __syncthreads();

        // S = Q K^T (4x4 per thread, float4 over d)
        float s[4][4];
        #pragma unroll
        for (int i = 0; i < 4; i++)
            #pragma unroll
            for (int j = 0; j < 4; j++) s[i][j] = 0.f;

        const float4* Q4 = reinterpret_cast<const float4*>(Qs);
        const float4* K4 = reinterpret_cast<const float4*>(Ks);
        #pragma unroll 4
        for (int d4 = 0; d4 < 16; d4++) {
            float4 q[4], k[4];
            #pragma unroll
            for (int i = 0; i < 4; i++) q[i] = Q4[(r0 + i) * 16 + d4];
            #pragma unroll
            for (int j = 0; j < 4; j++) k[j] = K4[(c0 + j) * 16 + d4];
            #pragma unroll
            for (int i = 0; i < 4; i++)
                #pragma unroll
                for (int j = 0; j < 4; j++)
                    s[i][j] += q[i].x * k[j].x + q[i].y * k[j].y
                             + q[i].z * k[j].z + q[i].w * k[j].w;
        }

        // Causal mask (only needed on the diagonal tile)
        if (kt == bx) {
            #pragma unroll
            for (int i = 0; i < 4; i++)
                #pragma unroll
                for (int j = 0; j < 4; j++)
                    if (c0 + j > r0 + i) s[i][j] = -INFINITY;
        }

        // Per-thread row-max partials
        #pragma unroll
        for (int i = 0; i < 4; i++) {
            float tm = fmaxf(fmaxf(s[i][0], s[i][1]), fmaxf(s[i][2], s[i][3]));
            red[(r0 + i) * 16 + tx] = tm;
        }
        __syncthreads();
        if (tid < 64) {
            float mc = red[tid * 16];
            #pragma unroll
            for (int k = 1; k < 16; k++) mc = fmaxf(mc, red[tid * 16 + k]);
            float mo = m_s[tid];
            float mn = fmaxf(mo, mc);
            a_s[tid] = __expf(mo - mn);
            m_s[tid] = mn;
        }
        __syncthreads();

        // P = exp(S - m); write over Ks; partial row sums
        #pragma unroll
        for (int i = 0; i < 4; i++) {
            float mrow = m_s[r0 + i];
            float psum = 0.f;
            #pragma unroll
            for (int j = 0; j < 4; j++) {
                float p = __expf(s[i][j] - mrow);
                Ks[(r0 + i) * 64 + c0 + j] = p;
                psum += p;
            }
            red[(r0 + i) * 16 + tx] = psum;
        }
        __syncthreads();
        if (tid < 64) {
            float ss = 0.f;
            #pragma unroll
            for (int k = 0; k < 16; k++) ss += red[tid * 16 + k];
            l_s[tid] = l_s[tid] * a_s[tid] + ss;
        }

        // O = O*alpha + P @ V
        #pragma unroll
        for (int i = 0; i < 4; i++) {
            float a = a_s[r0 + i];
            o4[i].x *= a; o4[i].y *= a; o4[i].z *= a; o4[i].w *= a;
        }
        const float4* V4 = reinterpret_cast<const float4*>(Vs);
        #pragma unroll 4
        for (int j = 0; j < 64; j++) {
            float4 v = V4[j * 16 + tx];
            #pragma unroll
            for (int i = 0; i < 4; i++) {
                float p = Ks[(r0 + i) * 64 + j];
                o4[i].x += p * v.x; o4[i].y += p * v.y;
                o4[i].z += p * v.z; o4[i].w += p * v.w;
            }
        }
    }
    __syncthreads();  // l_s final

    #pragma unroll
    for (int i = 0; i < 4; i++) {
        float inv = 1.f / l_s[r0 + i];
        float4 o = o4[i];
        o.x *= inv; o.y *= inv; o.z *= inv; o.w *= inv;
        *reinterpret_cast<float4*>(
            &g_y[((size_t)(b * T_ + q0 + r0 + i)) * C_ + h * HD_ + c0]) = o;
    }
}

// ---------------------------------------------------------------------------
extern "C" void kernel_launch(void* const* d_in, const int* in_sizes, int n_in,
                              void* d_out, int out_size)
{
    const float* x      = (const float*)d_in[0];
    const float* w_attn = (const float*)d_in[1];
    const float* b_attn = (const float*)d_in[2];
    const float* w_proj = (const float*)d_in[3];
    const float* b_proj = (const float*)d_in[4];
    float* out = (float*)d_out;

    float *qkv_ptr = nullptr, *y_ptr = nullptr;
    cudaGetSymbolAddress((void**)&qkv_ptr, g_qkv);
    cudaGetSymbolAddress((void**)&y_ptr,  g_y);

    cudaFuncSetAttribute(flash_kernel,
                         cudaFuncAttributeMaxDynamicSharedMemorySize,
                         FL_SMEM_BYTES);

    // 1) qkv = x @ w_attn + b_attn   (8192 x 2304 x 768)
    sgemm_bias_kernel<<<dim3(C3_ / 128, (B_ * T_) / 128), 256>>>(
        x, w_attn, b_attn, qkv_ptr, B_ * T_, C3_, C_);

    // 2) flash attention -> g_y  (B,T,C layout, heads interleaved by column)
    flash_kernel<<<dim3(T_ / 64, NH_, B_), 256, FL_SMEM_BYTES>>>();

    // 3) out = y @ w_proj + b_proj  (8192 x 768 x 768)
    sgemm_bias_kernel<<<dim3(C_ / 128, (B_ * T_) / 128), 256>>>(
        y_ptr, w_proj, b_proj, out, B_ * T_, C_, C_);
}

// round 2
// speedup vs baseline: 1.9400x; 1.9400x over previous
#include <cuda_runtime.h>
#include <math.h>

#define B_   2
#define T_   4096
#define C_   768
#define NH_  12
#define HD_  64
#define C3_  (3*C_)

// Scratch (allocation-free: __device__ globals)
__device__ float g_qkv[(size_t)B_*T_*C3_];   // 75.5 MB
__device__ float g_y[(size_t)B_*T_*C_];      // 25.2 MB

// ---------------------------------------------------------------------------
// Classic 128x128x8 SGEMM with bias: C[m][n] = sum_k A[m][k]*B[k][n] + bias[n]
// ---------------------------------------------------------------------------
__global__ __launch_bounds__(256) void sgemm_bias_kernel(
    const float* __restrict__ A, const float* __restrict__ Bm,
    const float* __restrict__ bias, float* __restrict__ Cm,
    int M, int N, int K)
{
    __shared__ float As[8][128];   // transposed A tile
    __shared__ float Bs[8][128];

    const int tid = threadIdx.x;
    const int m0 = blockIdx.y * 128;
    const int n0 = blockIdx.x * 128;
    const int tx = tid & 15, ty = tid >> 4;
    const int row0 = ty * 8, col0 = tx * 8;

    float acc[8][8];
    #pragma unroll
    for (int i = 0; i < 8; i++)
        #pragma unroll
        for (int j = 0; j < 8; j++) acc[i][j] = 0.f;

    const int aRow = tid >> 1, aCol = (tid & 1) * 4;
    const int bRow = tid >> 5, bCol = (tid & 31) * 4;

    for (int k0 = 0; k0 < K; k0 += 8) {
        float4 av = *reinterpret_cast<const float4*>(
            &A[(size_t)(m0 + aRow) * K + k0 + aCol]);
        float4 bv = *reinterpret_cast<const float4*>(
            &Bm[(size_t)(k0 + bRow) * N + n0 + bCol]);
        __syncthreads();
        As[aCol + 0][aRow] = av.x;
        As[aCol + 1][aRow] = av.y;
        As[aCol + 2][aRow] = av.z;
        As[aCol + 3][aRow] = av.w;
        *reinterpret_cast<float4*>(&Bs[bRow][bCol]) = bv;
        __syncthreads();
        #pragma unroll
        for (int kk = 0; kk < 8; kk++) {
            float a[8], b[8];
            #pragma unroll
            for (int i = 0; i < 8; i++) a[i] = As[kk][row0 + i];
            #pragma unroll
            for (int j = 0; j < 8; j++) b[j] = Bs[kk][col0 + j];
            #pragma unroll
            for (int i = 0; i < 8; i++)
                #pragma unroll
                for (int j = 0; j < 8; j++)
                    acc[i][j] += a[i] * b[j];
        }
    }

    #pragma unroll
    for (int i = 0; i < 8; i++) {
        #pragma unroll
        for (int j = 0; j < 8; j += 4) {
            float4 o;
            o.x = acc[i][j + 0] + bias[n0 + col0 + j + 0];
            o.y = acc[i][j + 1] + bias[n0 + col0 + j + 1];
            o.z = acc[i][j + 2] + bias[n0 + col0 + j + 2];
            o.w = acc[i][j + 3] + bias[n0 + col0 + j + 3];
            *reinterpret_cast<float4*>(
                &Cm[(size_t)(m0 + row0 + i) * N + n0 + col0 + j]) = o;
        }
    }
}

// ---------------------------------------------------------------------------
// Flash attention v2, fp32.
//  - XOR-swizzled smem (conflict-free LDS.128 everywhere)
//  - softmax stats in registers, butterfly shuffle reductions (no serial code)
//  - separate P buffer -> 3 syncs per k-tile
//  - heavy q-tiles scheduled first
// One block = (b, h, 64-query tile); 256 threads; 4x4 register tile.
// ---------------------------------------------------------------------------
#define FL_SMEM_BYTES (4 * 4096 * 4)   // Q,K,V,P tiles, 64KB

// swizzled float4 index inside a 64x64 tile: row in [0,64), chunk in [0,16)
__device__ __forceinline__ int SW(int row, int chunk) {
    return row * 16 + (chunk ^ ((row >> 2) & 15));
}

__global__ __launch_bounds__(256) void flash_kernel()
{
    extern __shared__ float smem[];
    float4* Q4 = reinterpret_cast<float4*>(smem);
    float4* K4 = Q4 + 1024;
    float4* V4 = K4 + 1024;
    float4* P4 = V4 + 1024;

    const int tid = threadIdx.x;
    const int qt = (gridDim.x - 1) - blockIdx.x;   // heavy tiles first
    const int h  = blockIdx.y;
    const int b  = blockIdx.z;
    const int q0 = qt * 64;

    const int tx = tid & 15, ty = tid >> 4;
    const int r0 = ty * 4, c0 = tx * 4;

    const int lr  = tid >> 4;       // load row base
    const int lc4 = tid & 15;       // load chunk
    const int lc  = lc4 * 4;

    // Load Q tile, pre-scaled by 1/sqrt(HD)=0.125
    #pragma unroll
    for (int it = 0; it < 4; it++) {
        int rr = lr + it * 16;
        float4 v = *reinterpret_cast<const float4*>(
            &g_qkv[((size_t)(b * T_ + q0 + rr)) * C3_ + h * HD_ + lc]);
        v.x *= 0.125f; v.y *= 0.125f; v.z *= 0.125f; v.w *= 0.125f;
        Q4[SW(rr, lc4)] = v;
    }

    float4 o4[4];
    float  m[4], l[4];
    #pragma unroll
    for (int i = 0; i < 4; i++) {
        o4[i] = make_float4(0.f, 0.f, 0.f, 0.f);
        m[i] = -INFINITY; l[i] = 0.f;
    }

    for (int kt = 0; kt <= qt; kt++) {
        __syncthreads();   // K/V (prev iter S-reads) + P (prev PV-reads) done
        // Load K,V tiles (swizzled)
        #pragma unroll
        for (int it = 0; it < 4; it++) {
            int rr = lr + it * 16;
            size_t base = ((size_t)(b * T_ + kt * 64 + rr)) * C3_ + h * HD_ + lc;
            K4[SW(rr, lc4)] = *reinterpret_cast<const float4*>(&g_qkv[C_ + base]);
            V4[SW(rr, lc4)] = *reinterpret_cast<const float4*>(&g_qkv[2 * C_ + base]);
        }
        __syncthreads();

        // S = Q K^T  (4x4 per thread, float4 over d)
        float s[4][4];
        #pragma unroll
        for (int i = 0; i < 4; i++)
            #pragma unroll
            for (int j = 0; j < 4; j++) s[i][j] = 0.f;

        #pragma unroll 4
        for (int d4 = 0; d4 < 16; d4++) {
            float4 q[4], k[4];
            #pragma unroll
            for (int i = 0; i < 4; i++) q[i] = Q4[SW(r0 + i, d4)];
            #pragma unroll
            for (int j = 0; j < 4; j++) k[j] = K4[SW(c0 + j, d4)];
            #pragma unroll
            for (int i = 0; i < 4; i++)
                #pragma unroll
                for (int j = 0; j < 4; j++)
                    s[i][j] += q[i].x * k[j].x + q[i].y * k[j].y
                             + q[i].z * k[j].z + q[i].w * k[j].w;
        }

        // Causal mask on diagonal tile
        if (kt == qt) {
            #pragma unroll
            for (int i = 0; i < 4; i++)
                #pragma unroll
                for (int j = 0; j < 4; j++)
                    if (c0 + j > r0 + i) s[i][j] = -INFINITY;
        }

        // Online softmax, all in registers + shuffles
        #pragma unroll
        for (int i = 0; i < 4; i++) {
            float tm = fmaxf(fmaxf(s[i][0], s[i][1]), fmaxf(s[i][2], s[i][3]));
            #pragma unroll
            for (int off = 8; off; off >>= 1)
                tm = fmaxf(tm, __shfl_xor_sync(0xffffffffu, tm, off));
            float mn = fmaxf(m[i], tm);
            float alpha = __expf(m[i] - mn);
            m[i] = mn;

            float4 p;
            p.x = __expf(s[i][0] - mn);
            p.y = __expf(s[i][1] - mn);
            p.z = __expf(s[i][2] - mn);
            p.w = __expf(s[i][3] - mn);
            float ps = (p.x + p.y) + (p.z + p.w);
            #pragma unroll
            for (int off = 8; off; off >>= 1)
                ps += __shfl_xor_sync(0xffffffffu, ps, off);
            l[i] = l[i] * alpha + ps;

            o4[i].x *= alpha; o4[i].y *= alpha;
            o4[i].z *= alpha; o4[i].w *= alpha;

            P4[SW(r0 + i, tx)] = p;
        }
        __syncthreads();

        // O += P @ V  (vectorized over j in chunks of 4)
        #pragma unroll 4
        for (int j4 = 0; j4 < 16; j4++) {
            float4 p[4];
            #pragma unroll
            for (int i = 0; i < 4; i++) p[i] = P4[SW(r0 + i, j4)];
            float4 v0 = V4[SW(j4 * 4 + 0, tx)];
            float4 v1 = V4[SW(j4 * 4 + 1, tx)];
            float4 v2 = V4[SW(j4 * 4 + 2, tx)];
            float4 v3 = V4[SW(j4 * 4 + 3, tx)];
            #pragma unroll
            for (int i = 0; i < 4; i++) {
                o4[i].x += p[i].x * v0.x; o4[i].y += p[i].x * v0.y;
                o4[i].z += p[i].x * v0.z; o4[i].w += p[i].x * v0.w;
                o4[i].x += p[i].y * v1.x; o4[i].y += p[i].y * v1.y;
                o4[i].z += p[i].y * v1.z; o4[i].w += p[i].y * v1.w;
                o4[i].x += p[i].z * v2.x; o4[i].y += p[i].z * v2.y;
                o4[i].z += p[i].z * v2.z; o4[i].w += p[i].z * v2.w;
                o4[i].x += p[i].w * v3.x; o4[i].y += p[i].w * v3.y;
                o4[i].z += p[i].w * v3.z; o4[i].w += p[i].w * v3.w;
            }
        }
    }

    #pragma unroll
    for (int i = 0; i < 4; i++) {
        float inv = 1.f / l[i];
        float4 o = o4[i];
        o.x *= inv; o.y *= inv; o.z *= inv; o.w *= inv;
        *reinterpret_cast<float4*>(
            &g_y[((size_t)(b * T_ + q0 + r0 + i)) * C_ + h * HD_ + c0]) = o;
    }
}

// ---------------------------------------------------------------------------
extern "C" void kernel_launch(void* const* d_in, const int* in_sizes, int n_in,
                              void* d_out, int out_size)
{
    const float* x      = (const float*)d_in[0];
    const float* w_attn = (const float*)d_in[1];
    const float* b_attn = (const float*)d_in[2];
    const float* w_proj = (const float*)d_in[3];
    const float* b_proj = (const float*)d_in[4];
    float* out = (float*)d_out;

    float *qkv_ptr = nullptr, *y_ptr = nullptr;
    cudaGetSymbolAddress((void**)&qkv_ptr, g_qkv);
    cudaGetSymbolAddress((void**)&y_ptr,  g_y);

    cudaFuncSetAttribute(flash_kernel,
                         cudaFuncAttributeMaxDynamicSharedMemorySize,
                         FL_SMEM_BYTES);

    // 1) qkv = x @ w_attn + b_attn   (8192 x 2304 x 768)
    sgemm_bias_kernel<<<dim3(C3_ / 128, (B_ * T_) / 128), 256>>>(
        x, w_attn, b_attn, qkv_ptr, B_ * T_, C3_, C_);

    // 2) flash attention -> g_y
    flash_kernel<<<dim3(T_ / 64, NH_, B_), 256, FL_SMEM_BYTES>>>();

    // 3) out = y @ w_proj + b_proj  (8192 x 768 x 768)
    sgemm_bias_kernel<<<dim3(C_ / 128, (B_ * T_) / 128), 256>>>(
        y_ptr, w_proj, b_proj, out, B_ * T_, C_, C_);
}

// round 3
// speedup vs baseline: 2.1096x; 1.0874x over previous
#include <cuda_runtime.h>
#include <math.h>

#define B_   2
#define T_   4096
#define C_   768
#define NH_  12
#define HD_  64
#define C3_  (3*C_)

typedef unsigned long long ull;

// Scratch (allocation-free: __device__ globals)
__device__ float g_qkv[(size_t)B_*T_*C3_];   // 75.5 MB
__device__ float g_y[(size_t)B_*T_*C_];      // 25.2 MB

// ---- packed f32x2 helpers (Blackwell FFMA2 path, inline PTX only) ----------
__device__ __forceinline__ void ffma2(ull& d, ull a, ull b) {
    asm("fma.rn.f32x2 %0, %1, %2, %0;" : "+l"(d) : "l"(a), "l"(b));
}
__device__ __forceinline__ void fmul2(ull& d, ull a) {
    asm("mul.rn.f32x2 %0, %0, %1;" : "+l"(d) : "l"(a));
}
__device__ __forceinline__ ull pack2(float x, float y) {
    ull r;
    asm("mov.b64 %0, {%1, %2};" : "=l"(r) : "f"(x), "f"(y));
    return r;
}
__device__ __forceinline__ float2 unpack2(ull v) {
    float2 r;
    asm("mov.b64 {%0, %1}, %2;" : "=f"(r.x), "=f"(r.y) : "l"(v));
    return r;
}

// ---------------------------------------------------------------------------
// 128x128x8 SGEMM with bias, FFMA2 inner loop.
// ---------------------------------------------------------------------------
__global__ __launch_bounds__(256) void sgemm_bias_kernel(
    const float* __restrict__ A, const float* __restrict__ Bm,
    const float* __restrict__ bias, float* __restrict__ Cm,
    int M, int N, int K)
{
    __shared__ float As[8][128];   // transposed A tile
    __shared__ float Bs[8][128];

    const int tid = threadIdx.x;
    const int m0 = blockIdx.y * 128;
    const int n0 = blockIdx.x * 128;
    const int tx = tid & 15, ty = tid >> 4;
    const int row0 = ty * 8, col0 = tx * 8;

    ull acc2[8][4];
    #pragma unroll
    for (int i = 0; i < 8; i++)
        #pragma unroll
        for (int j = 0; j < 4; j++) acc2[i][j] = 0ull;

    const int aRow = tid >> 1, aCol = (tid & 1) * 4;
    const int bRow = tid >> 5, bCol = (tid & 31) * 4;

    for (int k0 = 0; k0 < K; k0 += 8) {
        float4 av = *reinterpret_cast<const float4*>(
            &A[(size_t)(m0 + aRow) * K + k0 + aCol]);
        float4 bv = *reinterpret_cast<const float4*>(
            &Bm[(size_t)(k0 + bRow) * N + n0 + bCol]);
        __syncthreads();
        As[aCol + 0][aRow] = av.x;
        As[aCol + 1][aRow] = av.y;
        As[aCol + 2][aRow] = av.z;
        As[aCol + 3][aRow] = av.w;
        *reinterpret_cast<float4*>(&Bs[bRow][bCol]) = bv;
        __syncthreads();
        #pragma unroll
        for (int kk = 0; kk < 8; kk++) {
            float4 a0 = *reinterpret_cast<const float4*>(&As[kk][row0]);
            float4 a1 = *reinterpret_cast<const float4*>(&As[kk][row0 + 4]);
            ulonglong2 b0 = *reinterpret_cast<const ulonglong2*>(&Bs[kk][col0]);
            ulonglong2 b1 = *reinterpret_cast<const ulonglong2*>(&Bs[kk][col0 + 4]);
            ull ad[8];
            ad[0] = pack2(a0.x, a0.x); ad[1] = pack2(a0.y, a0.y);
            ad[2] = pack2(a0.z, a0.z); ad[3] = pack2(a0.w, a0.w);
            ad[4] = pack2(a1.x, a1.x); ad[5] = pack2(a1.y, a1.y);
            ad[6] = pack2(a1.z, a1.z); ad[7] = pack2(a1.w, a1.w);
            #pragma unroll
            for (int i = 0; i < 8; i++) {
                ffma2(acc2[i][0], ad[i], b0.x);
                ffma2(acc2[i][1], ad[i], b0.y);
                ffma2(acc2[i][2], ad[i], b1.x);
                ffma2(acc2[i][3], ad[i], b1.y);
            }
        }
    }

    #pragma unroll
    for (int i = 0; i < 8; i++) {
        #pragma unroll
        for (int j = 0; j < 2; j++) {
            float2 p0 = unpack2(acc2[i][j * 2 + 0]);
            float2 p1 = unpack2(acc2[i][j * 2 + 1]);
            float4 o;
            o.x = p0.x + bias[n0 + col0 + j * 4 + 0];
            o.y = p0.y + bias[n0 + col0 + j * 4 + 1];
            o.z = p1.x + bias[n0 + col0 + j * 4 + 2];
            o.w = p1.y + bias[n0 + col0 + j * 4 + 3];
            *reinterpret_cast<float4*>(
                &Cm[(size_t)(m0 + row0 + i) * N + n0 + col0 + j * 4]) = o;
        }
    }
}

// ---------------------------------------------------------------------------
// Flash attention v3: swizzled smem, register softmax, FFMA2 matmuls.
// ---------------------------------------------------------------------------
#define FL_SMEM_BYTES (4 * 4096 * 4)   // Q,K,V,P tiles, 64KB

__device__ __forceinline__ int SW(int row, int chunk) {
    return row * 16 + (chunk ^ ((row >> 2) & 15));
}

__global__ __launch_bounds__(256) void flash_kernel()
{
    extern __shared__ float smem[];
    float4* Q4 = reinterpret_cast<float4*>(smem);
    float4* K4 = Q4 + 1024;
    float4* V4 = K4 + 1024;
    float4* P4 = V4 + 1024;
    const ulonglong2* Q2 = reinterpret_cast<const ulonglong2*>(Q4);
    const ulonglong2* K2 = reinterpret_cast<const ulonglong2*>(K4);
    const ulonglong2* V2 = reinterpret_cast<const ulonglong2*>(V4);

    const int tid = threadIdx.x;
    const int qt = (gridDim.x - 1) - blockIdx.x;   // heavy tiles first
    const int h  = blockIdx.y;
    const int b  = blockIdx.z;
    const int q0 = qt * 64;

    const int tx = tid & 15, ty = tid >> 4;
    const int r0 = ty * 4, c0 = tx * 4;

    const int lr  = tid >> 4;
    const int lc4 = tid & 15;
    const int lc  = lc4 * 4;

    // Load Q tile, pre-scaled by 1/sqrt(HD)=0.125
    #pragma unroll
    for (int it = 0; it < 4; it++) {
        int rr = lr + it * 16;
        float4 v = *reinterpret_cast<const float4*>(
            &g_qkv[((size_t)(b * T_ + q0 + rr)) * C3_ + h * HD_ + lc]);
        v.x *= 0.125f; v.y *= 0.125f; v.z *= 0.125f; v.w *= 0.125f;
        Q4[SW(rr, lc4)] = v;
    }

    ull   o2[4][2];
    float m[4], l[4];
    #pragma unroll
    for (int i = 0; i < 4; i++) {
        o2[i][0] = 0ull; o2[i][1] = 0ull;
        m[i] = -INFINITY; l[i] = 0.f;
    }

    for (int kt = 0; kt <= qt; kt++) {
        __syncthreads();
        #pragma unroll
        for (int it = 0; it < 4; it++) {
            int rr = lr + it * 16;
            size_t base = ((size_t)(b * T_ + kt * 64 + rr)) * C3_ + h * HD_ + lc;
            K4[SW(rr, lc4)] = *reinterpret_cast<const float4*>(&g_qkv[C_ + base]);
            V4[SW(rr, lc4)] = *reinterpret_cast<const float4*>(&g_qkv[2 * C_ + base]);
        }
        __syncthreads();

        // S = Q K^T : accumulate d-pairs in packed f32x2
        ull s2[4][4];
        #pragma unroll
        for (int i = 0; i < 4; i++)
            #pragma unroll
            for (int j = 0; j < 4; j++) s2[i][j] = 0ull;

        #pragma unroll 4
        for (int d4 = 0; d4 < 16; d4++) {
            ulonglong2 q[4], k[4];
            #pragma unroll
            for (int i = 0; i < 4; i++) q[i] = Q2[SW(r0 + i, d4)];
            #pragma unroll
            for (int j = 0; j < 4; j++) k[j] = K2[SW(c0 + j, d4)];
            #pragma unroll
            for (int i = 0; i < 4; i++)
                #pragma unroll
                for (int j = 0; j < 4; j++) {
                    ffma2(s2[i][j], q[i].x, k[j].x);
                    ffma2(s2[i][j], q[i].y, k[j].y);
                }
        }

        float s[4][4];
        #pragma unroll
        for (int i = 0; i < 4; i++)
            #pragma unroll
            for (int j = 0; j < 4; j++) {
                float2 hv = unpack2(s2[i][j]);
                s[i][j] = hv.x + hv.y;
            }

        // Causal mask on diagonal tile
        if (kt == qt) {
            #pragma unroll
            for (int i = 0; i < 4; i++)
                #pragma unroll
                for (int j = 0; j < 4; j++)
                    if (c0 + j > r0 + i) s[i][j] = -INFINITY;
        }

        // Online softmax in registers + shuffles
        #pragma unroll
        for (int i = 0; i < 4; i++) {
            float tm = fmaxf(fmaxf(s[i][0], s[i][1]), fmaxf(s[i][2], s[i][3]));
            #pragma unroll
            for (int off = 8; off; off >>= 1)
                tm = fmaxf(tm, __shfl_xor_sync(0xffffffffu, tm, off));
            float mn = fmaxf(m[i], tm);
            float alpha = __expf(m[i] - mn);
            m[i] = mn;

            float4 p;
            p.x = __expf(s[i][0] - mn);
            p.y = __expf(s[i][1] - mn);
            p.z = __expf(s[i][2] - mn);
            p.w = __expf(s[i][3] - mn);
            float ps = (p.x + p.y) + (p.z + p.w);
            #pragma unroll
            for (int off = 8; off; off >>= 1)
                ps += __shfl_xor_sync(0xffffffffu, ps, off);
            l[i] = l[i] * alpha + ps;

            ull ad = pack2(alpha, alpha);
            fmul2(o2[i][0], ad);
            fmul2(o2[i][1], ad);

            P4[SW(r0 + i, tx)] = p;
        }
        __syncthreads();

        // O += P @ V (packed over head-dim pairs)
        #pragma unroll 4
        for (int j4 = 0; j4 < 16; j4++) {
            float4 p[4];
            #pragma unroll
            for (int i = 0; i < 4; i++) p[i] = P4[SW(r0 + i, j4)];
            ulonglong2 v0 = V2[SW(j4 * 4 + 0, tx)];
            ulonglong2 v1 = V2[SW(j4 * 4 + 1, tx)];
            ulonglong2 v2 = V2[SW(j4 * 4 + 2, tx)];
            ulonglong2 v3 = V2[SW(j4 * 4 + 3, tx)];
            #pragma unroll
            for (int i = 0; i < 4; i++) {
                ull pd;
                pd = pack2(p[i].x, p[i].x);
                ffma2(o2[i][0], pd, v0.x); ffma2(o2[i][1], pd, v0.y);
                pd = pack2(p[i].y, p[i].y);
                ffma2(o2[i][0], pd, v1.x); ffma2(o2[i][1], pd, v1.y);
                pd = pack2(p[i].z, p[i].z);
                ffma2(o2[i][0], pd, v2.x); ffma2(o2[i][1], pd, v2.y);
                pd = pack2(p[i].w, p[i].w);
                ffma2(o2[i][0], pd, v3.x); ffma2(o2[i][1], pd, v3.y);
            }
        }
    }

    #pragma unroll
    for (int i = 0; i < 4; i++) {
        float inv = 1.f / l[i];
        float2 pa = unpack2(o2[i][0]);
        float2 pb = unpack2(o2[i][1]);
        float4 o;
        o.x = pa.x * inv; o.y = pa.y * inv;
        o.z = pb.x * inv; o.w = pb.y * inv;
        *reinterpret_cast<float4*>(
            &g_y[((size_t)(b * T_ + q0 + r0 + i)) * C_ + h * HD_ + c0]) = o;
    }
}

// ---------------------------------------------------------------------------
extern "C" void kernel_launch(void* const* d_in, const int* in_sizes, int n_in,
                              void* d_out, int out_size)
{
    const float* x      = (const float*)d_in[0];
    const float* w_attn = (const float*)d_in[1];
    const float* b_attn = (const float*)d_in[2];
    const float* w_proj = (const float*)d_in[3];
    const float* b_proj = (const float*)d_in[4];
    float* out = (float*)d_out;

    float *qkv_ptr = nullptr, *y_ptr = nullptr;
    cudaGetSymbolAddress((void**)&qkv_ptr, g_qkv);
    cudaGetSymbolAddress((void**)&y_ptr,  g_y);

    cudaFuncSetAttribute(flash_kernel,
                         cudaFuncAttributeMaxDynamicSharedMemorySize,
                         FL_SMEM_BYTES);

    // 1) qkv = x @ w_attn + b_attn   (8192 x 2304 x 768)
    sgemm_bias_kernel<<<dim3(C3_ / 128, (B_ * T_) / 128), 256>>>(
        x, w_attn, b_attn, qkv_ptr, B_ * T_, C3_, C_);

    // 2) flash attention -> g_y
    flash_kernel<<<dim3(T_ / 64, NH_, B_), 256, FL_SMEM_BYTES>>>();

    // 3) out = y @ w_proj + b_proj  (8192 x 768 x 768)
    sgemm_bias_kernel<<<dim3(C_ / 128, (B_ * T_) / 128), 256>>>(
        y_ptr, w_proj, b_proj, out, B_ * T_, C_, C_);
}

// round 5
// speedup vs baseline: 2.4553x; 1.1639x over previous
#include <cuda_runtime.h>
#include <cuda_bf16.h>
#include <math.h>
#include <stdint.h>
#include <string.h>

#define B_   2
#define T_   4096
#define C_   768
#define NH_  12
#define HD_  64
#define C3_  (3*C_)
#define KE_  (3*C_)        // expanded split-K = 2304
#define M_   (B_*T_)       // 8192

typedef unsigned long long ull;

// Scratch (allocation-free: __device__ globals)
__device__ float g_qkv[(size_t)B_*T_*C3_];             // 75.5 MB
__device__ float g_y[(size_t)B_*T_*C_];                // 25.2 MB
__device__ __nv_bfloat16 g_aexp[(size_t)M_*KE_];       // 37.7 MB
__device__ __nv_bfloat16 g_b1exp[(size_t)C3_*KE_];     // 10.6 MB
__device__ __nv_bfloat16 g_b2exp[(size_t)C_*KE_];      //  3.5 MB

// ---- packed f32x2 helpers (flash kernel) -----------------------------------
__device__ __forceinline__ void ffma2(ull& d, ull a, ull b) {
    asm("fma.rn.f32x2 %0, %1, %2, %0;" : "+l"(d) : "l"(a), "l"(b));
}
__device__ __forceinline__ void fmul2(ull& d, ull a) {
    asm("mul.rn.f32x2 %0, %0, %1;" : "+l"(d) : "l"(a));
}
__device__ __forceinline__ ull pack2(float x, float y) {
    ull r; asm("mov.b64 %0, {%1, %2};" : "=l"(r) : "f"(x), "f"(y)); return r;
}
__device__ __forceinline__ float2 unpack2(ull v) {
    float2 r; asm("mov.b64 {%0, %1}, %2;" : "=f"(r.x), "=f"(r.y) : "l"(v)); return r;
}

__device__ __forceinline__ uint32_t smem_u32(const void* p) {
    uint32_t a;
    asm("{ .reg .u64 t; cvta.to.shared.u64 t, %1; cvt.u32.u64 %0, t; }" : "=r"(a) : "l"(p));
    return a;
}

// ---- warp-level tensor core ops (sm_80+ PTX, no 'a' features) --------------
__device__ __forceinline__ void ldsm4(uint32_t& r0, uint32_t& r1,
                                      uint32_t& r2, uint32_t& r3, uint32_t addr) {
    asm volatile("ldmatrix.sync.aligned.m8n8.x4.shared.b16 {%0,%1,%2,%3}, [%4];"
                 : "=r"(r0), "=r"(r1), "=r"(r2), "=r"(r3) : "r"(addr));
}
__device__ __forceinline__ void mma16816(float* c, const uint32_t* a,
                                         uint32_t b0, uint32_t b1) {
    asm volatile(
        "mma.sync.aligned.m16n8k16.row.col.f32.bf16.bf16.f32 "
        "{%0,%1,%2,%3}, {%4,%5,%6,%7}, {%8,%9}, {%0,%1,%2,%3};"
        : "+f"(c[0]), "+f"(c[1]), "+f"(c[2]), "+f"(c[3])
        : "r"(a[0]), "r"(a[1]), "r"(a[2]), "r"(a[3]), "r"(b0), "r"(b1));
}

static __device__ __forceinline__ ull pack4bf(__nv_bfloat16 a, __nv_bfloat16 b,
                                              __nv_bfloat16 c, __nv_bfloat16 d) {
    __nv_bfloat16 t[4] = {a, b, c, d};
    ull r; memcpy(&r, t, 8); return r;
}

// ---------------------------------------------------------------------------
// Prep: rows [R,K] fp32 -> [R,3K] bf16 as [hi | lo | hi]
// ---------------------------------------------------------------------------
__global__ void prep_split_rows(const float* __restrict__ in,
                                __nv_bfloat16* __restrict__ out, int R, int K)
{
    int i = blockIdx.x * blockDim.x + threadIdx.x;
    int total = (R * K) >> 2;
    if (i >= total) return;
    float4 v = reinterpret_cast<const float4*>(in)[i];
    int m = (i << 2) / K, k = (i << 2) % K;
    float a[4] = {v.x, v.y, v.z, v.w};
    __nv_bfloat16 h[4], l[4];
    #pragma unroll
    for (int j = 0; j < 4; j++) {
        h[j] = __float2bfloat16(a[j]);
        l[j] = __float2bfloat16(a[j] - __bfloat162float(h[j]));
    }
    ull H = pack4bf(h[0], h[1], h[2], h[3]);
    ull L = pack4bf(l[0], l[1], l[2], l[3]);
    size_t base = (size_t)m * (3 * K) + k;
    *reinterpret_cast<ull*>(&out[base])         = H;
    *reinterpret_cast<ull*>(&out[base + K])     = L;
    *reinterpret_cast<ull*>(&out[base + 2 * K]) = H;
}

// ---------------------------------------------------------------------------
// Prep: W [K,N] fp32 -> W^T expanded [N,3K] bf16 as [hi | hi | lo]
// ---------------------------------------------------------------------------
__global__ void prep_split_wt(const float* __restrict__ W,
                              __nv_bfloat16* __restrict__ out, int K, int N)
{
    int idx = blockIdx.x * blockDim.x + threadIdx.x;
    int total = N * (K >> 2);
    if (idx >= total) return;
    int k4 = idx / N;
    int n  = idx % N;
    __nv_bfloat16 h[4], l[4];
    #pragma unroll
    for (int j = 0; j < 4; j++) {
        float v = W[(size_t)(k4 * 4 + j) * N + n];
        h[j] = __float2bfloat16(v);
        l[j] = __float2bfloat16(v - __bfloat162float(h[j]));
    }
    ull H = pack4bf(h[0], h[1], h[2], h[3]);
    ull L = pack4bf(l[0], l[1], l[2], l[3]);
    size_t base = (size_t)n * (3 * K) + k4 * 4;
    *reinterpret_cast<ull*>(&out[base])         = H;
    *reinterpret_cast<ull*>(&out[base + K])     = H;
    *reinterpret_cast<ull*>(&out[base + 2 * K]) = L;
}

// ---------------------------------------------------------------------------
// mma.sync GEMM + bias: C[m][n] = sum_k Ae[m][k]*Be[n][k] + bias[n]
// CTA 128x128, K chunk 64. smem tiles SW128-swizzled, ldmatrix fragments.
// 8 warps in 4x2 grid; warp tile 32x64 = 2x8 m16n8k16 tiles.
// ---------------------------------------------------------------------------
#define G_SMEM_TOTAL (2 * 128 * 64 * 2)   // A + B tiles, 32KB

__global__ __launch_bounds__(256) void mma_gemm_bias(
    const __nv_bfloat16* __restrict__ Ae, const __nv_bfloat16* __restrict__ Be,
    const float* __restrict__ bias, float* __restrict__ Cm,
    int M, int N, int Ke)
{
    extern __shared__ char smem[];
    char* As = smem;                 // 128 rows x 128B
    char* Bs = smem + 16384;
    const uint32_t sA = smem_u32(As);
    const uint32_t sB = smem_u32(Bs);

    const int tid = threadIdx.x;
    const int wid = tid >> 5, lane = tid & 31;
    const int n0 = blockIdx.x * 128;
    const int m0 = blockIdx.y * 128;
    const int wm = wid & 3;          // m block (32 rows)
    const int wn = wid >> 2;         // n block (64 cols)

    float acc[2][8][4];
    #pragma unroll
    for (int t = 0; t < 2; t++)
        #pragma unroll
        for (int g = 0; g < 8; g++)
            #pragma unroll
            for (int e = 0; e < 4; e++) acc[t][g][e] = 0.f;

    // global->smem mapping
    const int r  = tid >> 3;         // 0..31
    const int c8 = tid & 7;          // 16B chunk

    // ldmatrix per-lane row offsets (within 16-row block): row = (lane&7) + ((lane>>3)&1)*8
    const int lrow = (lane & 7) + ((lane >> 3) & 1) * 8;
    const int lkc  = (lane >> 4);    // 0 or 1: which 8-bf16 k-half

    const int nchunks = Ke / 64;
    for (int ch = 0; ch < nchunks; ch++) {
        const int kb = ch * 64;
        __syncthreads();   // previous chunk's fragment reads done
        #pragma unroll
        for (int p = 0; p < 4; p++) {
            int rr = r + p * 32;
            uint32_t bo = (uint32_t)(rr * 128 + c8 * 16);
            uint32_t sw = bo ^ ((bo >> 3) & 0x70);
            *reinterpret_cast<float4*>(As + sw) = *reinterpret_cast<const float4*>(
                &Ae[(size_t)(m0 + rr) * Ke + kb + c8 * 8]);
            *reinterpret_cast<float4*>(Bs + sw) = *reinterpret_cast<const float4*>(
                &Be[(size_t)(n0 + rr) * Ke + kb + c8 * 8]);
        }
        __syncthreads();

        #pragma unroll
        for (int ks = 0; ks < 4; ks++) {
            const int cc = ks * 2 + lkc;   // 16B chunk for this lane
            // A fragments: 2 m16 tiles
            uint32_t a[2][4];
            #pragma unroll
            for (int t = 0; t < 2; t++) {
                int row = wm * 32 + t * 16 + lrow;
                uint32_t bo = (uint32_t)(row * 128 + cc * 16);
                uint32_t sw = bo ^ ((bo >> 3) & 0x70);
                ldsm4(a[t][0], a[t][1], a[t][2], a[t][3], sA + sw);
            }
            // B fragments: 4 n16 groups -> 8 n8 tiles
            #pragma unroll
            for (int g4 = 0; g4 < 4; g4++) {
                int row = wn * 64 + g4 * 16 + lrow;
                uint32_t bo = (uint32_t)(row * 128 + cc * 16);
                uint32_t sw = bo ^ ((bo >> 3) & 0x70);
                uint32_t b0, b1, b2, b3;
                ldsm4(b0, b1, b2, b3, sB + sw);
                #pragma unroll
                for (int t = 0; t < 2; t++) {
                    mma16816(acc[t][g4 * 2 + 0], a[t], b0, b2);
                    mma16816(acc[t][g4 * 2 + 1], a[t], b1, b3);
                }
            }
        }
    }

    // Epilogue: c-frag layout -> global with bias
    const int crow = lane >> 2;
    const int ccol = (lane & 3) * 2;
    #pragma unroll
    for (int t = 0; t < 2; t++) {
        #pragma unroll
        for (int g = 0; g < 8; g++) {
            int row = m0 + wm * 32 + t * 16 + crow;
            int col = n0 + wn * 64 + g * 8 + ccol;
            float2 bv = *reinterpret_cast<const float2*>(&bias[col]);
            float2 o0, o1;
            o0.x = acc[t][g][0] + bv.x; o0.y = acc[t][g][1] + bv.y;
            o1.x = acc[t][g][2] + bv.x; o1.y = acc[t][g][3] + bv.y;
            *reinterpret_cast<float2*>(&Cm[(size_t)row * N + col]) = o0;
            *reinterpret_cast<float2*>(&Cm[(size_t)(row + 8) * N + col]) = o1;
        }
    }
}

// ---------------------------------------------------------------------------
// Flash attention (unchanged from R3): swizzled smem, register softmax, FFMA2.
// ---------------------------------------------------------------------------
#define FL_SMEM_BYTES (4 * 4096 * 4)

__device__ __forceinline__ int SW(int row, int chunk) {
    return row * 16 + (chunk ^ ((row >> 2) & 15));
}

__global__ __launch_bounds__(256) void flash_kernel()
{
    extern __shared__ float fsmem[];
    float4* Q4 = reinterpret_cast<float4*>(fsmem);
    float4* K4 = Q4 + 1024;
    float4* V4 = K4 + 1024;
    float4* P4 = V4 + 1024;
    const ulonglong2* Q2 = reinterpret_cast<const ulonglong2*>(Q4);
    const ulonglong2* K2 = reinterpret_cast<const ulonglong2*>(K4);
    const ulonglong2* V2 = reinterpret_cast<const ulonglong2*>(V4);

    const int tid = threadIdx.x;
    const int qt = (gridDim.x - 1) - blockIdx.x;
    const int h  = blockIdx.y;
    const int b  = blockIdx.z;
    const int q0 = qt * 64;

    const int tx = tid & 15, ty = tid >> 4;
    const int r0 = ty * 4, c0 = tx * 4;

    const int lr  = tid >> 4;
    const int lc4 = tid & 15;
    const int lc  = lc4 * 4;

    #pragma unroll
    for (int it = 0; it < 4; it++) {
        int rr = lr + it * 16;
        float4 v = *reinterpret_cast<const float4*>(
            &g_qkv[((size_t)(b * T_ + q0 + rr)) * C3_ + h * HD_ + lc]);
        v.x *= 0.125f; v.y *= 0.125f; v.z *= 0.125f; v.w *= 0.125f;
        Q4[SW(rr, lc4)] = v;
    }

    ull   o2[4][2];
    float m[4], l[4];
    #pragma unroll
    for (int i = 0; i < 4; i++) {
        o2[i][0] = 0ull; o2[i][1] = 0ull;
        m[i] = -INFINITY; l[i] = 0.f;
    }

    for (int kt = 0; kt <= qt; kt++) {
        __syncthreads();
        #pragma unroll
        for (int it = 0; it < 4; it++) {
            int rr = lr + it * 16;
            size_t base = ((size_t)(b * T_ + kt * 64 + rr)) * C3_ + h * HD_ + lc;
            K4[SW(rr, lc4)] = *reinterpret_cast<const float4*>(&g_qkv[C_ + base]);
            V4[SW(rr, lc4)] = *reinterpret_cast<const float4*>(&g_qkv[2 * C_ + base]);
        }
        __syncthreads();

        ull s2[4][4];
        #pragma unroll
        for (int i = 0; i < 4; i++)
            #pragma unroll
            for (int j = 0; j < 4; j++) s2[i][j] = 0ull;

        #pragma unroll 4
        for (int d4 = 0; d4 < 16; d4++) {
            ulonglong2 q[4], k[4];
            #pragma unroll
            for (int i = 0; i < 4; i++) q[i] = Q2[SW(r0 + i, d4)];
            #pragma unroll
            for (int j = 0; j < 4; j++) k[j] = K2[SW(c0 + j, d4)];
            #pragma unroll
            for (int i = 0; i < 4; i++)
                #pragma unroll
                for (int j = 0; j < 4; j++) {
                    ffma2(s2[i][j], q[i].x, k[j].x);
                    ffma2(s2[i][j], q[i].y, k[j].y);
                }
        }

        float s[4][4];
        #pragma unroll
        for (int i = 0; i < 4; i++)
            #pragma unroll
            for (int j = 0; j < 4; j++) {
                float2 hv = unpack2(s2[i][j]);
                s[i][j] = hv.x + hv.y;
            }

        if (kt == qt) {
            #pragma unroll
            for (int i = 0; i < 4; i++)
                #pragma unroll
                for (int j = 0; j < 4; j++)
                    if (c0 + j > r0 + i) s[i][j] = -INFINITY;
        }

        #pragma unroll
        for (int i = 0; i < 4; i++) {
            float tm = fmaxf(fmaxf(s[i][0], s[i][1]), fmaxf(s[i][2], s[i][3]));
            #pragma unroll
            for (int off = 8; off; off >>= 1)
                tm = fmaxf(tm, __shfl_xor_sync(0xffffffffu, tm, off));
            float mn = fmaxf(m[i], tm);
            float alpha = __expf(m[i] - mn);
            m[i] = mn;

            float4 p;
            p.x = __expf(s[i][0] - mn);
            p.y = __expf(s[i][1] - mn);
            p.z = __expf(s[i][2] - mn);
            p.w = __expf(s[i][3] - mn);
            float ps = (p.x + p.y) + (p.z + p.w);
            #pragma unroll
            for (int off = 8; off; off >>= 1)
                ps += __shfl_xor_sync(0xffffffffu, ps, off);
            l[i] = l[i] * alpha + ps;

            ull ad = pack2(alpha, alpha);
            fmul2(o2[i][0], ad);
            fmul2(o2[i][1], ad);

            P4[SW(r0 + i, tx)] = p;
        }
        __syncthreads();

        #pragma unroll 4
        for (int j4 = 0; j4 < 16; j4++) {
            float4 p[4];
            #pragma unroll
            for (int i = 0; i < 4; i++) p[i] = P4[SW(r0 + i, j4)];
            ulonglong2 v0 = V2[SW(j4 * 4 + 0, tx)];
            ulonglong2 v1 = V2[SW(j4 * 4 + 1, tx)];
            ulonglong2 v2 = V2[SW(j4 * 4 + 2, tx)];
            ulonglong2 v3 = V2[SW(j4 * 4 + 3, tx)];
            #pragma unroll
            for (int i = 0; i < 4; i++) {
                ull pd;
                pd = pack2(p[i].x, p[i].x);
                ffma2(o2[i][0], pd, v0.x); ffma2(o2[i][1], pd, v0.y);
                pd = pack2(p[i].y, p[i].y);
                ffma2(o2[i][0], pd, v1.x); ffma2(o2[i][1], pd, v1.y);
                pd = pack2(p[i].z, p[i].z);
                ffma2(o2[i][0], pd, v2.x); ffma2(o2[i][1], pd, v2.y);
                pd = pack2(p[i].w, p[i].w);
                ffma2(o2[i][0], pd, v3.x); ffma2(o2[i][1], pd, v3.y);
            }
        }
    }

    #pragma unroll
    for (int i = 0; i < 4; i++) {
        float inv = 1.f / l[i];
        float2 pa = unpack2(o2[i][0]);
        float2 pb = unpack2(o2[i][1]);
        float4 o;
        o.x = pa.x * inv; o.y = pa.y * inv;
        o.z = pb.x * inv; o.w = pb.y * inv;
        *reinterpret_cast<float4*>(
            &g_y[((size_t)(b * T_ + q0 + r0 + i)) * C_ + h * HD_ + c0]) = o;
    }
}

// ---------------------------------------------------------------------------
extern "C" void kernel_launch(void* const* d_in, const int* in_sizes, int n_in,
                              void* d_out, int out_size)
{
    const float* x      = (const float*)d_in[0];
    const float* w_attn = (const float*)d_in[1];
    const float* b_attn = (const float*)d_in[2];
    const float* w_proj = (const float*)d_in[3];
    const float* b_proj = (const float*)d_in[4];
    float* out = (float*)d_out;

    float *qkv_ptr = nullptr, *y_ptr = nullptr;
    __nv_bfloat16 *aexp = nullptr, *b1exp = nullptr, *b2exp = nullptr;
    cudaGetSymbolAddress((void**)&qkv_ptr, g_qkv);
    cudaGetSymbolAddress((void**)&y_ptr,   g_y);
    cudaGetSymbolAddress((void**)&aexp,    g_aexp);
    cudaGetSymbolAddress((void**)&b1exp,   g_b1exp);
    cudaGetSymbolAddress((void**)&b2exp,   g_b2exp);

    cudaFuncSetAttribute(flash_kernel,
                         cudaFuncAttributeMaxDynamicSharedMemorySize, FL_SMEM_BYTES);
    cudaFuncSetAttribute(mma_gemm_bias,
                         cudaFuncAttributeMaxDynamicSharedMemorySize, G_SMEM_TOTAL);

    // Prep operands for GEMM1
    prep_split_rows<<<(M_ * C_ / 4 + 255) / 256, 256>>>(x, aexp, M_, C_);
    prep_split_wt<<<(C3_ * (C_ / 4) + 255) / 256, 256>>>(w_attn, b1exp, C_, C3_);

    // 1) qkv = x @ w_attn + b_attn  (mma.sync bf16 split-3)
    mma_gemm_bias<<<dim3(C3_ / 128, M_ / 128), 256, G_SMEM_TOTAL>>>(
        aexp, b1exp, b_attn, qkv_ptr, M_, C3_, KE_);

    // 2) flash attention -> g_y
    flash_kernel<<<dim3(T_ / 64, NH_, B_), 256, FL_SMEM_BYTES>>>();

    // Prep operands for GEMM2
    prep_split_rows<<<(M_ * C_ / 4 + 255) / 256, 256>>>(y_ptr, aexp, M_, C_);
    prep_split_wt<<<(C_ * (C_ / 4) + 255) / 256, 256>>>(w_proj, b2exp, C_, C_);

    // 3) out = y @ w_proj + b_proj  (mma.sync bf16 split-3)
    mma_gemm_bias<<<dim3(C_ / 128, M_ / 128), 256, G_SMEM_TOTAL>>>(
        aexp, b2exp, b_proj, out, M_, C_, KE_);
}

// round 6
// speedup vs baseline: 4.6327x; 1.8868x over previous
#include <cuda_runtime.h>
#include <cuda_bf16.h>
#include <math.h>
#include <stdint.h>
#include <string.h>

#define B_   2
#define T_   4096
#define C_   768
#define NH_  12
#define HD_  64
#define C3_  (3*C_)
#define KE_  (3*C_)        // expanded split-K = 2304
#define M_   (B_*T_)       // 8192

typedef unsigned long long ull;

// Scratch (allocation-free: __device__ globals)
// qkv in split bf16: [b][which(q/k/v)][h][part(hi/lo)][t][d]
__device__ __nv_bfloat16 g_qkvs[(size_t)B_*3*NH_*2*T_*HD_];  // 75.5 MB
__device__ float g_y[(size_t)B_*T_*C_];                      // 25.2 MB
__device__ __nv_bfloat16 g_aexp[(size_t)M_*KE_];             // 37.7 MB
__device__ __nv_bfloat16 g_b1exp[(size_t)C3_*KE_];           // 10.6 MB
__device__ __nv_bfloat16 g_b2exp[(size_t)C_*KE_];            //  3.5 MB

__device__ __forceinline__ uint32_t smem_u32(const void* p) {
    uint32_t a;
    asm("{ .reg .u64 t; cvta.to.shared.u64 t, %1; cvt.u32.u64 %0, t; }" : "=r"(a) : "l"(p));
    return a;
}

// ---- warp-level tensor core ops (sm_80+ PTX, no 'a' features) --------------
__device__ __forceinline__ void ldsm4(uint32_t& r0, uint32_t& r1,
                                      uint32_t& r2, uint32_t& r3, uint32_t addr) {
    asm volatile("ldmatrix.sync.aligned.m8n8.x4.shared.b16 {%0,%1,%2,%3}, [%4];"
                 : "=r"(r0), "=r"(r1), "=r"(r2), "=r"(r3) : "r"(addr));
}
__device__ __forceinline__ void ldsm4t(uint32_t& r0, uint32_t& r1,
                                       uint32_t& r2, uint32_t& r3, uint32_t addr) {
    asm volatile("ldmatrix.sync.aligned.m8n8.x4.trans.shared.b16 {%0,%1,%2,%3}, [%4];"
                 : "=r"(r0), "=r"(r1), "=r"(r2), "=r"(r3) : "r"(addr));
}
__device__ __forceinline__ void mma16816(float* c, const uint32_t* a,
                                         uint32_t b0, uint32_t b1) {
    asm volatile(
        "mma.sync.aligned.m16n8k16.row.col.f32.bf16.bf16.f32 "
        "{%0,%1,%2,%3}, {%4,%5,%6,%7}, {%8,%9}, {%0,%1,%2,%3};"
        : "+f"(c[0]), "+f"(c[1]), "+f"(c[2]), "+f"(c[3])
        : "r"(a[0]), "r"(a[1]), "r"(a[2]), "r"(a[3]), "r"(b0), "r"(b1));
}

// split two fp32 into packed bf16 hi pair + lo (residual) pair
__device__ __forceinline__ void bfsplit2(float p0, float p1, uint32_t& hi, uint32_t& lo) {
    asm("cvt.rn.bf16x2.f32 %0, %1, %2;" : "=r"(hi) : "f"(p1), "f"(p0));
    float h0 = __uint_as_float(hi << 16);
    float h1 = __uint_as_float(hi & 0xffff0000u);
    asm("cvt.rn.bf16x2.f32 %0, %1, %2;" : "=r"(lo) : "f"(p1 - h1), "f"(p0 - h0));
}

static __device__ __forceinline__ ull pack4bf(__nv_bfloat16 a, __nv_bfloat16 b,
                                              __nv_bfloat16 c, __nv_bfloat16 d) {
    __nv_bfloat16 t[4] = {a, b, c, d};
    ull r; memcpy(&r, t, 8); return r;
}

// ---------------------------------------------------------------------------
// Prep: rows [R,K] fp32 -> [R,3K] bf16 as [hi | lo | hi]
// ---------------------------------------------------------------------------
__global__ void prep_split_rows(const float* __restrict__ in,
                                __nv_bfloat16* __restrict__ out, int R, int K)
{
    int i = blockIdx.x * blockDim.x + threadIdx.x;
    int total = (R * K) >> 2;
    if (i >= total) return;
    float4 v = reinterpret_cast<const float4*>(in)[i];
    int m = (i << 2) / K, k = (i << 2) % K;
    float a[4] = {v.x, v.y, v.z, v.w};
    __nv_bfloat16 h[4], l[4];
    #pragma unroll
    for (int j = 0; j < 4; j++) {
        h[j] = __float2bfloat16(a[j]);
        l[j] = __float2bfloat16(a[j] - __bfloat162float(h[j]));
    }
    ull H = pack4bf(h[0], h[1], h[2], h[3]);
    ull L = pack4bf(l[0], l[1], l[2], l[3]);
    size_t base = (size_t)m * (3 * K) + k;
    *reinterpret_cast<ull*>(&out[base])         = H;
    *reinterpret_cast<ull*>(&out[base + K])     = L;
    *reinterpret_cast<ull*>(&out[base + 2 * K]) = H;
}

// ---------------------------------------------------------------------------
// Prep: W [K,N] fp32 -> W^T expanded [N,3K] bf16 as [hi | hi | lo]
// ---------------------------------------------------------------------------
__global__ void prep_split_wt(const float* __restrict__ W,
                              __nv_bfloat16* __restrict__ out, int K, int N)
{
    int idx = blockIdx.x * blockDim.x + threadIdx.x;
    int total = N * (K >> 2);
    if (idx >= total) return;
    int k4 = idx / N;
    int n  = idx % N;
    __nv_bfloat16 h[4], l[4];
    #pragma unroll
    for (int j = 0; j < 4; j++) {
        float v = W[(size_t)(k4 * 4 + j) * N + n];
        h[j] = __float2bfloat16(v);
        l[j] = __float2bfloat16(v - __bfloat162float(h[j]));
    }
    ull H = pack4bf(h[0], h[1], h[2], h[3]);
    ull L = pack4bf(l[0], l[1], l[2], l[3]);
    size_t base = (size_t)n * (3 * K) + k4 * 4;
    *reinterpret_cast<ull*>(&out[base])         = H;
    *reinterpret_cast<ull*>(&out[base + K])     = H;
    *reinterpret_cast<ull*>(&out[base + 2 * K]) = L;
}

// ---------------------------------------------------------------------------
// mma.sync GEMM mainloop (shared by both epilogues)
// CTA 128x128, K chunk 64. SW128 smem, 8 warps 4x2, warp 32x64.
// ---------------------------------------------------------------------------
#define G_SMEM_TOTAL (2 * 128 * 64 * 2)   // A + B tiles, 32KB

struct GemmCore {
    float acc[2][8][4];
    int wm, wn, lane;
};

__device__ __forceinline__ void gemm_mainloop(
    GemmCore& gc, char* As, char* Bs,
    const __nv_bfloat16* Ae, const __nv_bfloat16* Be,
    int m0, int n0, int Ke, int tid)
{
    const uint32_t sA = smem_u32(As);
    const uint32_t sB = smem_u32(Bs);
    const int lane = gc.lane;
    const int r  = tid >> 3;
    const int c8 = tid & 7;
    const int lrow = (lane & 7) + ((lane >> 3) & 1) * 8;
    const int lkc  = (lane >> 4);

    #pragma unroll
    for (int t = 0; t < 2; t++)
        #pragma unroll
        for (int g = 0; g < 8; g++)
            #pragma unroll
            for (int e = 0; e < 4; e++) gc.acc[t][g][e] = 0.f;

    const int nchunks = Ke / 64;
    for (int ch = 0; ch < nchunks; ch++) {
        const int kb = ch * 64;
        __syncthreads();
        #pragma unroll
        for (int p = 0; p < 4; p++) {
            int rr = r + p * 32;
            uint32_t bo = (uint32_t)(rr * 128 + c8 * 16);
            uint32_t sw = bo ^ ((bo >> 3) & 0x70);
            *reinterpret_cast<float4*>(As + sw) = *reinterpret_cast<const float4*>(
                &Ae[(size_t)(m0 + rr) * Ke + kb + c8 * 8]);
            *reinterpret_cast<float4*>(Bs + sw) = *reinterpret_cast<const float4*>(
                &Be[(size_t)(n0 + rr) * Ke + kb + c8 * 8]);
        }
        __syncthreads();

        #pragma unroll
        for (int ks = 0; ks < 4; ks++) {
            const int cc = ks * 2 + lkc;
            uint32_t a[2][4];
            #pragma unroll
            for (int t = 0; t < 2; t++) {
                int row = gc.wm * 32 + t * 16 + lrow;
                uint32_t bo = (uint32_t)(row * 128 + cc * 16);
                uint32_t sw = bo ^ ((bo >> 3) & 0x70);
                ldsm4(a[t][0], a[t][1], a[t][2], a[t][3], sA + sw);
            }
            #pragma unroll
            for (int g4 = 0; g4 < 4; g4++) {
                int row = gc.wn * 64 + g4 * 16 + lrow;
                uint32_t bo = (uint32_t)(row * 128 + cc * 16);
                uint32_t sw = bo ^ ((bo >> 3) & 0x70);
                uint32_t b0, b1, b2, b3;
                ldsm4(b0, b1, b2, b3, sB + sw);
                #pragma unroll
                for (int t = 0; t < 2; t++) {
                    mma16816(gc.acc[t][g4 * 2 + 0], a[t], b0, b2);
                    mma16816(gc.acc[t][g4 * 2 + 1], a[t], b1, b3);
                }
            }
        }
    }
}

// GEMM2: fp32 output with bias
__global__ __launch_bounds__(256) void mma_gemm_bias(
    const __nv_bfloat16* __restrict__ Ae, const __nv_bfloat16* __restrict__ Be,
    const float* __restrict__ bias, float* __restrict__ Cm,
    int M, int N, int Ke)
{
    extern __shared__ char smem[];
    const int tid = threadIdx.x;
    GemmCore gc; gc.wm = (tid >> 5) & 3; gc.wn = tid >> 7; gc.lane = tid & 31;
    const int n0 = blockIdx.x * 128;
    const int m0 = blockIdx.y * 128;
    gemm_mainloop(gc, smem, smem + 16384, Ae, Be, m0, n0, Ke, tid);

    const int crow = gc.lane >> 2;
    const int ccol = (gc.lane & 3) * 2;
    #pragma unroll
    for (int t = 0; t < 2; t++) {
        #pragma unroll
        for (int g = 0; g < 8; g++) {
            int row = m0 + gc.wm * 32 + t * 16 + crow;
            int col = n0 + gc.wn * 64 + g * 8 + ccol;
            float2 bv = *reinterpret_cast<const float2*>(&bias[col]);
            float2 o0, o1;
            o0.x = gc.acc[t][g][0] + bv.x; o0.y = gc.acc[t][g][1] + bv.y;
            o1.x = gc.acc[t][g][2] + bv.x; o1.y = gc.acc[t][g][3] + bv.y;
            *reinterpret_cast<float2*>(&Cm[(size_t)row * N + col]) = o0;
            *reinterpret_cast<float2*>(&Cm[(size_t)(row + 8) * N + col]) = o1;
        }
    }
}

// GEMM1: writes split bf16 qkv (q pre-scaled by 1/8)
__device__ __forceinline__ void store_qkv_pair(int bb, int which, int hh,
                                               int t, int dd, float v0, float v1)
{
    uint32_t hi, lo;
    bfsplit2(v0, v1, hi, lo);
    size_t base = ((((size_t)bb * 3 + which) * NH_ + hh) * 2) * T_ * HD_
                + (size_t)t * HD_ + dd;
    *reinterpret_cast<uint32_t*>(&g_qkvs[base]) = hi;
    *reinterpret_cast<uint32_t*>(&g_qkvs[base + (size_t)T_ * HD_]) = lo;
}

__global__ __launch_bounds__(256) void mma_gemm_qkv(
    const __nv_bfloat16* __restrict__ Ae, const __nv_bfloat16* __restrict__ Be,
    const float* __restrict__ bias, int Ke)
{
    extern __shared__ char smem[];
    const int tid = threadIdx.x;
    GemmCore gc; gc.wm = (tid >> 5) & 3; gc.wn = tid >> 7; gc.lane = tid & 31;
    const int n0 = blockIdx.x * 128;
    const int m0 = blockIdx.y * 128;
    gemm_mainloop(gc, smem, smem + 16384, Ae, Be, m0, n0, Ke, tid);

    const int crow = gc.lane >> 2;
    const int ccol = (gc.lane & 3) * 2;
    #pragma unroll
    for (int t = 0; t < 2; t++) {
        #pragma unroll
        for (int g = 0; g < 8; g++) {
            int row = m0 + gc.wm * 32 + t * 16 + crow;
            int col = n0 + gc.wn * 64 + g * 8 + ccol;
            int which = col / 768, hh = (col % 768) / 64, dd = col % 64;
            int bb = row >> 12, tt = row & 4095;
            float2 bv = *reinterpret_cast<const float2*>(&bias[col]);
            float sc_ = (which == 0) ? 0.125f : 1.f;
            float v0 = (gc.acc[t][g][0] + bv.x) * sc_;
            float v1 = (gc.acc[t][g][1] + bv.y) * sc_;
            float v2 = (gc.acc[t][g][2] + bv.x) * sc_;
            float v3 = (gc.acc[t][g][3] + bv.y) * sc_;
            store_qkv_pair(bb, which, hh, tt,     dd, v0, v1);
            store_qkv_pair(bb, which, hh, tt + 8, dd, v2, v3);
        }
    }
}

// ---------------------------------------------------------------------------
// Flash attention v4: mma.sync, Q frags in regs, P in regs, 3-term splits.
// CTA = 128 q-rows x (b,h); 8 warps, warp = 16q x 64k. smem 32KB.
// ---------------------------------------------------------------------------
#define FL_SMEM_BYTES 32768
// k-loop layout: Khi@0, Klo@8K, Vhi@16K, Vlo@24K  (64 rows x 128B each)
// Q staging (before k-loop): Qhi@0 (16K), Qlo@16K (16K)  (128 rows x 128B)

__global__ __launch_bounds__(256) void flash_kernel()
{
    extern __shared__ char fsm[];
    const uint32_t sb = smem_u32(fsm);

    const int tid  = threadIdx.x;
    const int w    = tid >> 5;
    const int lane = tid & 31;
    const int qt   = (gridDim.x - 1) - blockIdx.x;   // heavy tiles first
    const int h    = blockIdx.y;
    const int b    = blockIdx.z;
    const int q0   = qt * 128;

    const int lrow = (lane & 7) + ((lane >> 3) & 1) * 8;
    const int lkc  = lane >> 4;

    // ---- stage Q (hi/lo) into smem, swizzled ----
    {
        const int part = tid >> 7;          // 0 hi, 1 lo
        const int ql   = tid & 127;
        const int c8   = ql & 7;
        const int r16  = ql >> 3;           // 0..15
        const __nv_bfloat16* src = g_qkvs +
            ((((size_t)b * 3 + 0) * NH_ + h) * 2 + part) * (size_t)T_ * HD_;
        char* dst = fsm + part * 16384;
        #pragma unroll
        for (int p = 0; p < 8; p++) {
            int rr = p * 16 + r16;
            uint32_t sw = (uint32_t)(rr * 128 + ((c8 ^ (rr & 7)) * 16));
            *reinterpret_cast<float4*>(dst + sw) = *reinterpret_cast<const float4*>(
                &src[(size_t)(q0 + rr) * HD_ + c8 * 8]);
        }
    }
    __syncthreads();

    // ---- preload Q fragments: qf[0..3]=hi ksteps, qf[4..7]=lo ksteps ----
    uint32_t qf[8][4];
    #pragma unroll
    for (int part = 0; part < 2; part++) {
        #pragma unroll
        for (int ks = 0; ks < 4; ks++) {
            int row = w * 16 + lrow;
            int cc = ks * 2 + lkc;
            uint32_t sw = (uint32_t)(part * 16384 + row * 128 + ((cc ^ (row & 7)) * 16));
            uint32_t* q = qf[part * 4 + ks];
            ldsm4(q[0], q[1], q[2], q[3], sb + sw);
        }
    }

    float oc[8][4];
    #pragma unroll
    for (int t = 0; t < 8; t++)
        #pragma unroll
        for (int e = 0; e < 4; e++) oc[t][e] = 0.f;
    float mst[2] = {-INFINITY, -INFINITY};
    float lst[2] = {0.f, 0.f};

    // K/V global load mapping
    const int tt  = tid >> 6;            // tile 0..3: Khi,Klo,Vhi,Vlo
    const int ll  = tid & 63;
    const int kc8 = ll & 7;
    const int kr8 = ll >> 3;             // 0..7
    const int kwhich = 1 + (tt >> 1);
    const int kpart  = tt & 1;
    const __nv_bfloat16* kvsrc = g_qkvs +
        ((((size_t)b * 3 + kwhich) * NH_ + h) * 2 + kpart) * (size_t)T_ * HD_;
    char* kvdst = fsm + tt * 8192;

    const int ktmax = 2 * qt + 2;
    for (int kt = 0; kt < ktmax; kt++) {
        __syncthreads();   // prior ldsm reads done before overwrite
        #pragma unroll
        for (int p = 0; p < 8; p++) {
            int rr = p * 8 + kr8;
            uint32_t sw = (uint32_t)(rr * 128 + ((kc8 ^ (rr & 7)) * 16));
            *reinterpret_cast<float4*>(kvdst + sw) = *reinterpret_cast<const float4*>(
                &kvsrc[(size_t)(kt * 64 + rr) * HD_ + kc8 * 8]);
        }
        __syncthreads();

        if (kt * 64 > q0 + w * 16 + 15) continue;   // warp fully masked

        // ---- S = Q K^T (3-term split) ----
        float sc[8][4];
        #pragma unroll
        for (int t = 0; t < 8; t++)
            #pragma unroll
            for (int e = 0; e < 4; e++) sc[t][e] = 0.f;

        #pragma unroll
        for (int ks = 0; ks < 4; ks++) {
            const int cc = ks * 2 + lkc;
            #pragma unroll
            for (int g = 0; g < 4; g++) {
                int row = g * 16 + lrow;
                uint32_t sw = (uint32_t)(row * 128 + ((cc ^ (row & 7)) * 16));
                uint32_t b0, b1, b2, b3;
                ldsm4(b0, b1, b2, b3, sb + sw);          // K_hi
                mma16816(sc[2 * g + 0], qf[ks], b0, b2);
                mma16816(sc[2 * g + 1], qf[ks], b1, b3);
                mma16816(sc[2 * g + 0], qf[4 + ks], b0, b2);   // Q_lo * K_hi
                mma16816(sc[2 * g + 1], qf[4 + ks], b1, b3);
            }
        }
        #pragma unroll
        for (int ks = 0; ks < 4; ks++) {
            const int cc = ks * 2 + lkc;
            #pragma unroll
            for (int g = 0; g < 4; g++) {
                int row = g * 16 + lrow;
                uint32_t sw = (uint32_t)(8192 + row * 128 + ((cc ^ (row & 7)) * 16));
                uint32_t b0, b1, b2, b3;
                ldsm4(b0, b1, b2, b3, sb + sw);          // K_lo
                mma16816(sc[2 * g + 0], qf[ks], b0, b2); // Q_hi * K_lo
                mma16816(sc[2 * g + 1], qf[ks], b1, b3);
            }
        }

        // ---- causal mask ----
        if (kt * 64 + 63 > q0 + w * 16) {
            #pragma unroll
            for (int t = 0; t < 8; t++)
                #pragma unroll
                for (int e = 0; e < 4; e++) {
                    int gr = q0 + w * 16 + (lane >> 2) + ((e >= 2) ? 8 : 0);
                    int gcc = kt * 64 + t * 8 + 2 * (lane & 3) + (e & 1);
                    if (gcc > gr) sc[t][e] = -INFINITY;
                }
        }

        // ---- online softmax (warp-local) ----
        #pragma unroll
        for (int h2 = 0; h2 < 2; h2++) {
            const int e0 = h2 * 2;
            float tm = -INFINITY;
            #pragma unroll
            for (int t = 0; t < 8; t++)
                tm = fmaxf(tm, fmaxf(sc[t][e0], sc[t][e0 + 1]));
            tm = fmaxf(tm, __shfl_xor_sync(0xffffffffu, tm, 1));
            tm = fmaxf(tm, __shfl_xor_sync(0xffffffffu, tm, 2));
            float mn = fmaxf(mst[h2], tm);
            float alpha = __expf(mst[h2] - mn);
            mst[h2] = mn;
            float ps = 0.f;
            #pragma unroll
            for (int t = 0; t < 8; t++) {
                float p0 = __expf(sc[t][e0] - mn);
                float p1 = __expf(sc[t][e0 + 1] - mn);
                sc[t][e0] = p0; sc[t][e0 + 1] = p1;
                ps += p0 + p1;
            }
            ps += __shfl_xor_sync(0xffffffffu, ps, 1);
            ps += __shfl_xor_sync(0xffffffffu, ps, 2);
            lst[h2] = lst[h2] * alpha + ps;
            #pragma unroll
            for (int t = 0; t < 8; t++) {
                oc[t][e0] *= alpha; oc[t][e0 + 1] *= alpha;
            }
        }

        // ---- pack P into A-fragments (hi + lo) ----
        uint32_t ph[4][4], pl[4][4];
        #pragma unroll
        for (int j = 0; j < 4; j++) {
            bfsplit2(sc[2 * j][0],     sc[2 * j][1],     ph[j][0], pl[j][0]);
            bfsplit2(sc[2 * j][2],     sc[2 * j][3],     ph[j][1], pl[j][1]);
            bfsplit2(sc[2 * j + 1][0], sc[2 * j + 1][1], ph[j][2], pl[j][2]);
            bfsplit2(sc[2 * j + 1][2], sc[2 * j + 1][3], ph[j][3], pl[j][3]);
        }

        // ---- O += P V (3-term split), V via ldmatrix.trans ----
        #pragma unroll
        for (int j = 0; j < 4; j++) {
            #pragma unroll
            for (int g = 0; g < 4; g++) {
                int row = j * 16 + lrow;
                int cc = g * 2 + lkc;
                uint32_t swz = (uint32_t)(row * 128 + ((cc ^ (row & 7)) * 16));
                uint32_t v0, v1, v2, v3;
                ldsm4t(v0, v1, v2, v3, sb + 16384 + swz);   // V_hi
                mma16816(oc[2 * g + 0], ph[j], v0, v1);
                mma16816(oc[2 * g + 1], ph[j], v2, v3);
                mma16816(oc[2 * g + 0], pl[j], v0, v1);     // P_lo * V_hi
                mma16816(oc[2 * g + 1], pl[j], v2, v3);
                uint32_t u0, u1, u2, u3;
                ldsm4t(u0, u1, u2, u3, sb + 24576 + swz);   // V_lo
                mma16816(oc[2 * g + 0], ph[j], u0, u1);     // P_hi * V_lo
                mma16816(oc[2 * g + 1], ph[j], u2, u3);
            }
        }
    }

    // ---- epilogue: O / l -> g_y ----
    float inv0 = 1.f / lst[0];
    float inv1 = 1.f / lst[1];
    #pragma unroll
    for (int t = 0; t < 8; t++) {
        int row = q0 + w * 16 + (lane >> 2);
        int d0  = t * 8 + 2 * (lane & 3);
        float2 o0, o1;
        o0.x = oc[t][0] * inv0; o0.y = oc[t][1] * inv0;
        o1.x = oc[t][2] * inv1; o1.y = oc[t][3] * inv1;
        *reinterpret_cast<float2*>(
            &g_y[((size_t)(b * T_ + row)) * C_ + h * HD_ + d0]) = o0;
        *reinterpret_cast<float2*>(
            &g_y[((size_t)(b * T_ + row + 8)) * C_ + h * HD_ + d0]) = o1;
    }
}

// ---------------------------------------------------------------------------
extern "C" void kernel_launch(void* const* d_in, const int* in_sizes, int n_in,
                              void* d_out, int out_size)
{
    const float* x      = (const float*)d_in[0];
    const float* w_attn = (const float*)d_in[1];
    const float* b_attn = (const float*)d_in[2];
    const float* w_proj = (const float*)d_in[3];
    const float* b_proj = (const float*)d_in[4];
    float* out = (float*)d_out;

    float* y_ptr = nullptr;
    __nv_bfloat16 *aexp = nullptr, *b1exp = nullptr, *b2exp = nullptr;
    cudaGetSymbolAddress((void**)&y_ptr,  g_y);
    cudaGetSymbolAddress((void**)&aexp,   g_aexp);
    cudaGetSymbolAddress((void**)&b1exp,  g_b1exp);
    cudaGetSymbolAddress((void**)&b2exp,  g_b2exp);

    cudaFuncSetAttribute(flash_kernel,
                         cudaFuncAttributeMaxDynamicSharedMemorySize, FL_SMEM_BYTES);
    cudaFuncSetAttribute(mma_gemm_bias,
                         cudaFuncAttributeMaxDynamicSharedMemorySize, G_SMEM_TOTAL);
    cudaFuncSetAttribute(mma_gemm_qkv,
                         cudaFuncAttributeMaxDynamicSharedMemorySize, G_SMEM_TOTAL);

    // Prep operands for GEMM1
    prep_split_rows<<<(M_ * C_ / 4 + 255) / 256, 256>>>(x, aexp, M_, C_);
    prep_split_wt<<<(C3_ * (C_ / 4) + 255) / 256, 256>>>(w_attn, b1exp, C_, C3_);

    // 1) qkv = x @ w_attn + b_attn -> split bf16 q/k/v (q scaled)
    mma_gemm_qkv<<<dim3(C3_ / 128, M_ / 128), 256, G_SMEM_TOTAL>>>(
        aexp, b1exp, b_attn, KE_);

    // 2) flash attention (mma.sync) -> g_y
    flash_kernel<<<dim3(T_ / 128, NH_, B_), 256, FL_SMEM_BYTES>>>();

    // Prep operands for GEMM2
    prep_split_rows<<<(M_ * C_ / 4 + 255) / 256, 256>>>(y_ptr, aexp, M_, C_);
    prep_split_wt<<<(C_ * (C_ / 4) + 255) / 256, 256>>>(w_proj, b2exp, C_, C_);

    // 3) out = y @ w_proj + b_proj
    mma_gemm_bias<<<dim3(C_ / 128, M_ / 128), 256, G_SMEM_TOTAL>>>(
        aexp, b2exp, b_proj, out, M_, C_, KE_);
}

// round 7
// speedup vs baseline: 6.2712x; 1.3537x over previous
#include <cuda_runtime.h>
#include <cuda_bf16.h>
#include <math.h>
#include <stdint.h>
#include <string.h>

#define B_   2
#define T_   4096
#define C_   768
#define NH_  12
#define HD_  64
#define C3_  (3*C_)
#define KE_  (3*C_)        // expanded split-K = 2304
#define M_   (B_*T_)       // 8192

typedef unsigned long long ull;

// Scratch (allocation-free: __device__ globals)
// qkv in split bf16: [b][which(q/k/v)][h][part(hi/lo)][t][d]
__device__ __nv_bfloat16 g_qkvs[(size_t)B_*3*NH_*2*T_*HD_];  // 75.5 MB
__device__ __nv_bfloat16 g_aexp[(size_t)M_*KE_];             // 37.7 MB (x-split, then y-split)
__device__ __nv_bfloat16 g_b1exp[(size_t)C3_*KE_];           // 10.6 MB
__device__ __nv_bfloat16 g_b2exp[(size_t)C_*KE_];            //  3.5 MB

__device__ __forceinline__ uint32_t smem_u32(const void* p) {
    uint32_t a;
    asm("{ .reg .u64 t; cvta.to.shared.u64 t, %1; cvt.u32.u64 %0, t; }" : "=r"(a) : "l"(p));
    return a;
}

// ---- cp.async helpers ------------------------------------------------------
__device__ __forceinline__ void cpa16(uint32_t dst, const void* src) {
    asm volatile("cp.async.cg.shared.global [%0], [%1], 16;" :: "r"(dst), "l"(src));
}
#define CP_COMMIT() asm volatile("cp.async.commit_group;" ::: "memory")
#define CP_WAIT1()  asm volatile("cp.async.wait_group 1;" ::: "memory")
#define CP_WAIT0()  asm volatile("cp.async.wait_group 0;" ::: "memory")

// ---- warp-level tensor core ops --------------------------------------------
__device__ __forceinline__ void ldsm4(uint32_t& r0, uint32_t& r1,
                                      uint32_t& r2, uint32_t& r3, uint32_t addr) {
    asm volatile("ldmatrix.sync.aligned.m8n8.x4.shared.b16 {%0,%1,%2,%3}, [%4];"
                 : "=r"(r0), "=r"(r1), "=r"(r2), "=r"(r3) : "r"(addr));
}
__device__ __forceinline__ void ldsm4t(uint32_t& r0, uint32_t& r1,
                                       uint32_t& r2, uint32_t& r3, uint32_t addr) {
    asm volatile("ldmatrix.sync.aligned.m8n8.x4.trans.shared.b16 {%0,%1,%2,%3}, [%4];"
                 : "=r"(r0), "=r"(r1), "=r"(r2), "=r"(r3) : "r"(addr));
}
__device__ __forceinline__ void mma16816(float* c, const uint32_t* a,
                                         uint32_t b0, uint32_t b1) {
    asm volatile(
        "mma.sync.aligned.m16n8k16.row.col.f32.bf16.bf16.f32 "
        "{%0,%1,%2,%3}, {%4,%5,%6,%7}, {%8,%9}, {%0,%1,%2,%3};"
        : "+f"(c[0]), "+f"(c[1]), "+f"(c[2]), "+f"(c[3])
        : "r"(a[0]), "r"(a[1]), "r"(a[2]), "r"(a[3]), "r"(b0), "r"(b1));
}

// split two fp32 into packed bf16 hi pair + lo (residual) pair
__device__ __forceinline__ void bfsplit2(float p0, float p1, uint32_t& hi, uint32_t& lo) {
    asm("cvt.rn.bf16x2.f32 %0, %1, %2;" : "=r"(hi) : "f"(p1), "f"(p0));
    float h0 = __uint_as_float(hi << 16);
    float h1 = __uint_as_float(hi & 0xffff0000u);
    asm("cvt.rn.bf16x2.f32 %0, %1, %2;" : "=r"(lo) : "f"(p1 - h1), "f"(p0 - h0));
}

static __device__ __forceinline__ ull pack4bf(__nv_bfloat16 a, __nv_bfloat16 b,
                                              __nv_bfloat16 c, __nv_bfloat16 d) {
    __nv_bfloat16 t[4] = {a, b, c, d};
    ull r; memcpy(&r, t, 8); return r;
}

// ---------------------------------------------------------------------------
// Prep: rows [R,K] fp32 -> [R,3K] bf16 as [hi | lo | hi]
// ---------------------------------------------------------------------------
__global__ void prep_split_rows(const float* __restrict__ in,
                                __nv_bfloat16* __restrict__ out, int R, int K)
{
    int i = blockIdx.x * blockDim.x + threadIdx.x;
    int total = (R * K) >> 2;
    if (i >= total) return;
    float4 v = reinterpret_cast<const float4*>(in)[i];
    int m = (i << 2) / K, k = (i << 2) % K;
    float a[4] = {v.x, v.y, v.z, v.w};
    __nv_bfloat16 h[4], l[4];
    #pragma unroll
    for (int j = 0; j < 4; j++) {
        h[j] = __float2bfloat16(a[j]);
        l[j] = __float2bfloat16(a[j] - __bfloat162float(h[j]));
    }
    ull H = pack4bf(h[0], h[1], h[2], h[3]);
    ull L = pack4bf(l[0], l[1], l[2], l[3]);
    size_t base = (size_t)m * (3 * K) + k;
    *reinterpret_cast<ull*>(&out[base])         = H;
    *reinterpret_cast<ull*>(&out[base + K])     = L;
    *reinterpret_cast<ull*>(&out[base + 2 * K]) = H;
}

// ---------------------------------------------------------------------------
// Prep: W [K,N] fp32 -> W^T expanded [N,3K] bf16 as [hi | hi | lo]
// ---------------------------------------------------------------------------
__global__ void prep_split_wt(const float* __restrict__ W,
                              __nv_bfloat16* __restrict__ out, int K, int N)
{
    int idx = blockIdx.x * blockDim.x + threadIdx.x;
    int total = N * (K >> 2);
    if (idx >= total) return;
    int k4 = idx / N;
    int n  = idx % N;
    __nv_bfloat16 h[4], l[4];
    #pragma unroll
    for (int j = 0; j < 4; j++) {
        float v = W[(size_t)(k4 * 4 + j) * N + n];
        h[j] = __float2bfloat16(v);
        l[j] = __float2bfloat16(v - __bfloat162float(h[j]));
    }
    ull H = pack4bf(h[0], h[1], h[2], h[3]);
    ull L = pack4bf(l[0], l[1], l[2], l[3]);
    size_t base = (size_t)n * (3 * K) + k4 * 4;
    *reinterpret_cast<ull*>(&out[base])         = H;
    *reinterpret_cast<ull*>(&out[base + K])     = H;
    *reinterpret_cast<ull*>(&out[base + 2 * K]) = L;
}

// ---------------------------------------------------------------------------
// mma.sync GEMM mainloop with 2-stage cp.async double buffering.
// CTA 128x128, K chunk 64; buffers: A @ buf*32768, B @ buf*32768+16384.
// ---------------------------------------------------------------------------
#define G_SMEM_TOTAL 65536

struct GemmCore {
    float acc[2][8][4];
    int wm, wn, lane;
};

__device__ __forceinline__ void gemm_mainloop(
    GemmCore& gc, char* smem,
    const __nv_bfloat16* Ae, const __nv_bfloat16* Be,
    int m0, int n0, int Ke, int tid)
{
    const uint32_t sbase = smem_u32(smem);
    const int lane = gc.lane;
    const int r  = tid >> 3;
    const int c8 = tid & 7;
    const int lrow = (lane & 7) + ((lane >> 3) & 1) * 8;
    const int lkc  = (lane >> 4);

    #pragma unroll
    for (int t = 0; t < 2; t++)
        #pragma unroll
        for (int g = 0; g < 8; g++)
            #pragma unroll
            for (int e = 0; e < 4; e++) gc.acc[t][g][e] = 0.f;

    const int nchunks = Ke / 64;

    // prologue: issue chunk 0 into buf 0
    {
        #pragma unroll
        for (int p = 0; p < 4; p++) {
            int rr = r + p * 32;
            uint32_t bo = (uint32_t)(rr * 128 + c8 * 16);
            uint32_t sw = bo ^ ((bo >> 3) & 0x70);
            cpa16(sbase + sw,         &Ae[(size_t)(m0 + rr) * Ke + c8 * 8]);
            cpa16(sbase + 16384 + sw, &Be[(size_t)(n0 + rr) * Ke + c8 * 8]);
        }
        CP_COMMIT();
    }

    for (int ch = 0; ch < nchunks; ch++) {
        if (ch + 1 < nchunks) {
            const int kb = (ch + 1) * 64;
            const uint32_t bofs = (uint32_t)(((ch + 1) & 1) * 32768);
            #pragma unroll
            for (int p = 0; p < 4; p++) {
                int rr = r + p * 32;
                uint32_t bo = (uint32_t)(rr * 128 + c8 * 16);
                uint32_t sw = bo ^ ((bo >> 3) & 0x70);
                cpa16(sbase + bofs + sw,         &Ae[(size_t)(m0 + rr) * Ke + kb + c8 * 8]);
                cpa16(sbase + bofs + 16384 + sw, &Be[(size_t)(n0 + rr) * Ke + kb + c8 * 8]);
            }
            CP_COMMIT();
            CP_WAIT1();
        } else {
            CP_WAIT0();
        }
        __syncthreads();

        const uint32_t sA = sbase + (uint32_t)((ch & 1) * 32768);
        const uint32_t sB = sA + 16384;

        #pragma unroll
        for (int ks = 0; ks < 4; ks++) {
            const int cc = ks * 2 + lkc;
            uint32_t a[2][4];
            #pragma unroll
            for (int t = 0; t < 2; t++) {
                int row = gc.wm * 32 + t * 16 + lrow;
                uint32_t bo = (uint32_t)(row * 128 + cc * 16);
                uint32_t sw = bo ^ ((bo >> 3) & 0x70);
                ldsm4(a[t][0], a[t][1], a[t][2], a[t][3], sA + sw);
            }
            #pragma unroll
            for (int g4 = 0; g4 < 4; g4++) {
                int row = gc.wn * 64 + g4 * 16 + lrow;
                uint32_t bo = (uint32_t)(row * 128 + cc * 16);
                uint32_t sw = bo ^ ((bo >> 3) & 0x70);
                uint32_t b0, b1, b2, b3;
                ldsm4(b0, b1, b2, b3, sB + sw);
                #pragma unroll
                for (int t = 0; t < 2; t++) {
                    mma16816(gc.acc[t][g4 * 2 + 0], a[t], b0, b2);
                    mma16816(gc.acc[t][g4 * 2 + 1], a[t], b1, b3);
                }
            }
        }
        __syncthreads();   // compute done before next load overwrites this buf
    }
}

// GEMM2: fp32 output with bias
__global__ __launch_bounds__(256) void mma_gemm_bias(
    const __nv_bfloat16* __restrict__ Ae, const __nv_bfloat16* __restrict__ Be,
    const float* __restrict__ bias, float* __restrict__ Cm,
    int M, int N, int Ke)
{
    extern __shared__ char smem[];
    const int tid = threadIdx.x;
    GemmCore gc; gc.wm = (tid >> 5) & 3; gc.wn = tid >> 7; gc.lane = tid & 31;
    const int n0 = blockIdx.x * 128;
    const int m0 = blockIdx.y * 128;
    gemm_mainloop(gc, smem, Ae, Be, m0, n0, Ke, tid);

    const int crow = gc.lane >> 2;
    const int ccol = (gc.lane & 3) * 2;
    #pragma unroll
    for (int t = 0; t < 2; t++) {
        #pragma unroll
        for (int g = 0; g < 8; g++) {
            int row = m0 + gc.wm * 32 + t * 16 + crow;
            int col = n0 + gc.wn * 64 + g * 8 + ccol;
            float2 bv = *reinterpret_cast<const float2*>(&bias[col]);
            float2 o0, o1;
            o0.x = gc.acc[t][g][0] + bv.x; o0.y = gc.acc[t][g][1] + bv.y;
            o1.x = gc.acc[t][g][2] + bv.x; o1.y = gc.acc[t][g][3] + bv.y;
            *reinterpret_cast<float2*>(&Cm[(size_t)row * N + col]) = o0;
            *reinterpret_cast<float2*>(&Cm[(size_t)(row + 8) * N + col]) = o1;
        }
    }
}

// GEMM1: writes split bf16 qkv (q pre-scaled by 1/8)
__device__ __forceinline__ void store_qkv_pair(int bb, int which, int hh,
                                               int t, int dd, float v0, float v1)
{
    uint32_t hi, lo;
    bfsplit2(v0, v1, hi, lo);
    size_t base = ((((size_t)bb * 3 + which) * NH_ + hh) * 2) * T_ * HD_
                + (size_t)t * HD_ + dd;
    *reinterpret_cast<uint32_t*>(&g_qkvs[base]) = hi;
    *reinterpret_cast<uint32_t*>(&g_qkvs[base + (size_t)T_ * HD_]) = lo;
}

__global__ __launch_bounds__(256) void mma_gemm_qkv(
    const __nv_bfloat16* __restrict__ Ae, const __nv_bfloat16* __restrict__ Be,
    const float* __restrict__ bias, int Ke)
{
    extern __shared__ char smem[];
    const int tid = threadIdx.x;
    GemmCore gc; gc.wm = (tid >> 5) & 3; gc.wn = tid >> 7; gc.lane = tid & 31;
    const int n0 = blockIdx.x * 128;
    const int m0 = blockIdx.y * 128;
    gemm_mainloop(gc, smem, Ae, Be, m0, n0, Ke, tid);

    const int crow = gc.lane >> 2;
    const int ccol = (gc.lane & 3) * 2;
    #pragma unroll
    for (int t = 0; t < 2; t++) {
        #pragma unroll
        for (int g = 0; g < 8; g++) {
            int row = m0 + gc.wm * 32 + t * 16 + crow;
            int col = n0 + gc.wn * 64 + g * 8 + ccol;
            int which = col / 768, hh = (col % 768) / 64, dd = col % 64;
            int bb = row >> 12, tt = row & 4095;
            float2 bv = *reinterpret_cast<const float2*>(&bias[col]);
            float sc_ = (which == 0) ? 0.125f : 1.f;
            float v0 = (gc.acc[t][g][0] + bv.x) * sc_;
            float v1 = (gc.acc[t][g][1] + bv.y) * sc_;
            float v2 = (gc.acc[t][g][2] + bv.x) * sc_;
            float v3 = (gc.acc[t][g][3] + bv.y) * sc_;
            store_qkv_pair(bb, which, hh, tt,     dd, v0, v1);
            store_qkv_pair(bb, which, hh, tt + 8, dd, v2, v3);
        }
    }
}

// ---------------------------------------------------------------------------
// Flash attention v5: mma.sync + cp.async 2-stage K/V pipeline.
// CTA = 128 q-rows x (b,h); 8 warps, warp = 16q x 64k. smem 64KB.
// Buffer layout (32KB each): Khi@0, Klo@8K, Vhi@16K, Vlo@24K.
// Epilogue writes y directly as split bf16 rows into g_aexp [hi|lo|hi].
// ---------------------------------------------------------------------------
#define FL_SMEM_BYTES 65536

__global__ __launch_bounds__(256) void flash_kernel()
{
    extern __shared__ char fsm[];
    const uint32_t sb = smem_u32(fsm);

    const int tid  = threadIdx.x;
    const int w    = tid >> 5;
    const int lane = tid & 31;
    const int qt   = (gridDim.x - 1) - blockIdx.x;   // heavy tiles first
    const int h    = blockIdx.y;
    const int b    = blockIdx.z;
    const int q0   = qt * 128;

    const int lrow = (lane & 7) + ((lane >> 3) & 1) * 8;
    const int lkc  = lane >> 4;

    // K/V cp.async mapping: 4 tiles (Khi,Klo,Vhi,Vlo), 64 threads each
    const int tt  = tid >> 6;
    const int ll  = tid & 63;
    const int kc8 = ll & 7;
    const int kr8 = ll >> 3;
    const int kwhich = 1 + (tt >> 1);
    const int kpart  = tt & 1;
    const __nv_bfloat16* kvsrc = g_qkvs +
        ((((size_t)b * 3 + kwhich) * NH_ + h) * 2 + kpart) * (size_t)T_ * HD_;
    const uint32_t kvdst = sb + tt * 8192;

    const int ktmax = 2 * qt + 2;

    // prologue: issue K/V tile 0 into buf 0 (overlaps Q staging)
    #pragma unroll
    for (int p = 0; p < 8; p++) {
        int rr = p * 8 + kr8;
        uint32_t sw = (uint32_t)(rr * 128 + ((kc8 ^ (rr & 7)) * 16));
        cpa16(kvdst + sw, &kvsrc[(size_t)rr * HD_ + kc8 * 8]);
    }
    CP_COMMIT();

    // ---- stage Q (hi/lo) into buf1 region, swizzled ----
    {
        const int part = tid >> 7;
        const int ql   = tid & 127;
        const int c8   = ql & 7;
        const int r16  = ql >> 3;
        const __nv_bfloat16* src = g_qkvs +
            ((((size_t)b * 3 + 0) * NH_ + h) * 2 + part) * (size_t)T_ * HD_;
        char* dst = fsm + 32768 + part * 16384;
        #pragma unroll
        for (int p = 0; p < 8; p++) {
            int rr = p * 16 + r16;
            uint32_t sw = (uint32_t)(rr * 128 + ((c8 ^ (rr & 7)) * 16));
            *reinterpret_cast<float4*>(dst + sw) = *reinterpret_cast<const float4*>(
                &src[(size_t)(q0 + rr) * HD_ + c8 * 8]);
        }
    }
    __syncthreads();

    // ---- preload Q fragments: qf[0..3]=hi ksteps, qf[4..7]=lo ksteps ----
    uint32_t qf[8][4];
    #pragma unroll
    for (int part = 0; part < 2; part++) {
        #pragma unroll
        for (int ks = 0; ks < 4; ks++) {
            int row = w * 16 + lrow;
            int cc = ks * 2 + lkc;
            uint32_t sw = (uint32_t)(32768 + part * 16384 + row * 128
                                     + ((cc ^ (row & 7)) * 16));
            uint32_t* q = qf[part * 4 + ks];
            ldsm4(q[0], q[1], q[2], q[3], sb + sw);
        }
    }
    __syncthreads();   // buf1 reads done before tile1 cp.async writes it

    float oc[8][4];
    #pragma unroll
    for (int t = 0; t < 8; t++)
        #pragma unroll
        for (int e = 0; e < 4; e++) oc[t][e] = 0.f;
    float mst[2] = {-INFINITY, -INFINITY};
    float lst[2] = {0.f, 0.f};

    for (int kt = 0; kt < ktmax; kt++) {
        if (kt + 1 < ktmax) {
            const uint32_t bofs = (uint32_t)(((kt + 1) & 1) * 32768);
            #pragma unroll
            for (int p = 0; p < 8; p++) {
                int rr = p * 8 + kr8;
                uint32_t sw = (uint32_t)(rr * 128 + ((kc8 ^ (rr & 7)) * 16));
                cpa16(kvdst + bofs + sw,
                      &kvsrc[(size_t)((kt + 1) * 64 + rr) * HD_ + kc8 * 8]);
            }
            CP_COMMIT();
            CP_WAIT1();
        } else {
            CP_WAIT0();
        }
        __syncthreads();

        const uint32_t bb_ = sb + (uint32_t)((kt & 1) * 32768);

        if (kt * 64 <= q0 + w * 16 + 15) {
            // ---- S = Q K^T (3-term split) ----
            float sc[8][4];
            #pragma unroll
            for (int t = 0; t < 8; t++)
                #pragma unroll
                for (int e = 0; e < 4; e++) sc[t][e] = 0.f;

            #pragma unroll
            for (int ks = 0; ks < 4; ks++) {
                const int cc = ks * 2 + lkc;
                #pragma unroll
                for (int g = 0; g < 4; g++) {
                    int row = g * 16 + lrow;
                    uint32_t swz = (uint32_t)(row * 128 + ((cc ^ (row & 7)) * 16));
                    uint32_t b0, b1, b2, b3;
                    ldsm4(b0, b1, b2, b3, bb_ + swz);           // K_hi
                    mma16816(sc[2 * g + 0], qf[ks], b0, b2);
                    mma16816(sc[2 * g + 1], qf[ks], b1, b3);
                    mma16816(sc[2 * g + 0], qf[4 + ks], b0, b2);
                    mma16816(sc[2 * g + 1], qf[4 + ks], b1, b3);
                    uint32_t c0, c1, c2, c3;
                    ldsm4(c0, c1, c2, c3, bb_ + 8192 + swz);    // K_lo
                    mma16816(sc[2 * g + 0], qf[ks], c0, c2);
                    mma16816(sc[2 * g + 1], qf[ks], c1, c3);
                }
            }

            // ---- causal mask ----
            if (kt * 64 + 63 > q0 + w * 16) {
                #pragma unroll
                for (int t = 0; t < 8; t++)
                    #pragma unroll
                    for (int e = 0; e < 4; e++) {
                        int gr = q0 + w * 16 + (lane >> 2) + ((e >= 2) ? 8 : 0);
                        int gcc = kt * 64 + t * 8 + 2 * (lane & 3) + (e & 1);
                        if (gcc > gr) sc[t][e] = -INFINITY;
                    }
            }

            // ---- online softmax (warp-local) ----
            #pragma unroll
            for (int h2 = 0; h2 < 2; h2++) {
                const int e0 = h2 * 2;
                float tm = -INFINITY;
                #pragma unroll
                for (int t = 0; t < 8; t++)
                    tm = fmaxf(tm, fmaxf(sc[t][e0], sc[t][e0 + 1]));
                tm = fmaxf(tm, __shfl_xor_sync(0xffffffffu, tm, 1));
                tm = fmaxf(tm, __shfl_xor_sync(0xffffffffu, tm, 2));
                float mn = fmaxf(mst[h2], tm);
                float alpha = __expf(mst[h2] - mn);
                mst[h2] = mn;
                float ps = 0.f;
                #pragma unroll
                for (int t = 0; t < 8; t++) {
                    float p0 = __expf(sc[t][e0] - mn);
                    float p1 = __expf(sc[t][e0 + 1] - mn);
                    sc[t][e0] = p0; sc[t][e0 + 1] = p1;
                    ps += p0 + p1;
                }
                ps += __shfl_xor_sync(0xffffffffu, ps, 1);
                ps += __shfl_xor_sync(0xffffffffu, ps, 2);
                lst[h2] = lst[h2] * alpha + ps;
                #pragma unroll
                for (int t = 0; t < 8; t++) {
                    oc[t][e0] *= alpha; oc[t][e0 + 1] *= alpha;
                }
            }

            // ---- pack P into A-fragments (hi + lo) ----
            uint32_t ph[4][4], pl[4][4];
            #pragma unroll
            for (int j = 0; j < 4; j++) {
                bfsplit2(sc[2 * j][0],     sc[2 * j][1],     ph[j][0], pl[j][0]);
                bfsplit2(sc[2 * j][2],     sc[2 * j][3],     ph[j][1], pl[j][1]);
                bfsplit2(sc[2 * j + 1][0], sc[2 * j + 1][1], ph[j][2], pl[j][2]);
                bfsplit2(sc[2 * j + 1][2], sc[2 * j + 1][3], ph[j][3], pl[j][3]);
            }

            // ---- O += P V (3-term split) ----
            #pragma unroll
            for (int j = 0; j < 4; j++) {
                #pragma unroll
                for (int g = 0; g < 4; g++) {
                    int row = j * 16 + lrow;
                    int cc = g * 2 + lkc;
                    uint32_t swz = (uint32_t)(row * 128 + ((cc ^ (row & 7)) * 16));
                    uint32_t v0, v1, v2, v3;
                    ldsm4t(v0, v1, v2, v3, bb_ + 16384 + swz);  // V_hi
                    mma16816(oc[2 * g + 0], ph[j], v0, v1);
                    mma16816(oc[2 * g + 1], ph[j], v2, v3);
                    mma16816(oc[2 * g + 0], pl[j], v0, v1);
                    mma16816(oc[2 * g + 1], pl[j], v2, v3);
                    uint32_t u0, u1, u2, u3;
                    ldsm4t(u0, u1, u2, u3, bb_ + 24576 + swz);  // V_lo
                    mma16816(oc[2 * g + 0], ph[j], u0, u1);
                    mma16816(oc[2 * g + 1], ph[j], u2, u3);
                }
            }
        }
        __syncthreads();   // compute done before next load overwrites this buf
    }

    // ---- epilogue: O / l -> split bf16 rows of g_aexp [hi | lo | hi] ----
    float inv0 = 1.f / lst[0];
    float inv1 = 1.f / lst[1];
    #pragma unroll
    for (int t = 0; t < 8; t++) {
        int row = q0 + w * 16 + (lane >> 2);
        int d0  = t * 8 + 2 * (lane & 3);
        float a0 = oc[t][0] * inv0, a1 = oc[t][1] * inv0;
        float b0 = oc[t][2] * inv1, b1 = oc[t][3] * inv1;
        uint32_t hi, lo;
        size_t base0 = (size_t)(b * T_ + row) * KE_ + h * HD_ + d0;
        bfsplit2(a0, a1, hi, lo);
        *reinterpret_cast<uint32_t*>(&g_aexp[base0])          = hi;
        *reinterpret_cast<uint32_t*>(&g_aexp[base0 + C_])     = lo;
        *reinterpret_cast<uint32_t*>(&g_aexp[base0 + 2 * C_]) = hi;
        size_t base1 = base0 + (size_t)8 * KE_;
        bfsplit2(b0, b1, hi, lo);
        *reinterpret_cast<uint32_t*>(&g_aexp[base1])          = hi;
        *reinterpret_cast<uint32_t*>(&g_aexp[base1 + C_])     = lo;
        *reinterpret_cast<uint32_t*>(&g_aexp[base1 + 2 * C_]) = hi;
    }
}

// ---------------------------------------------------------------------------
extern "C" void kernel_launch(void* const* d_in, const int* in_sizes, int n_in,
                              void* d_out, int out_size)
{
    const float* x      = (const float*)d_in[0];
    const float* w_attn = (const float*)d_in[1];
    const float* b_attn = (const float*)d_in[2];
    const float* w_proj = (const float*)d_in[3];
    const float* b_proj = (const float*)d_in[4];
    float* out = (float*)d_out;

    __nv_bfloat16 *aexp = nullptr, *b1exp = nullptr, *b2exp = nullptr;
    cudaGetSymbolAddress((void**)&aexp,   g_aexp);
    cudaGetSymbolAddress((void**)&b1exp,  g_b1exp);
    cudaGetSymbolAddress((void**)&b2exp,  g_b2exp);

    cudaFuncSetAttribute(flash_kernel,
                         cudaFuncAttributeMaxDynamicSharedMemorySize, FL_SMEM_BYTES);
    cudaFuncSetAttribute(mma_gemm_bias,
                         cudaFuncAttributeMaxDynamicSharedMemorySize, G_SMEM_TOTAL);
    cudaFuncSetAttribute(mma_gemm_qkv,
                         cudaFuncAttributeMaxDynamicSharedMemorySize, G_SMEM_TOTAL);

    // Prep operands
    prep_split_rows<<<(M_ * C_ / 4 + 255) / 256, 256>>>(x, aexp, M_, C_);
    prep_split_wt<<<(C3_ * (C_ / 4) + 255) / 256, 256>>>(w_attn, b1exp, C_, C3_);
    prep_split_wt<<<(C_ * (C_ / 4) + 255) / 256, 256>>>(w_proj, b2exp, C_, C_);

    // 1) qkv = x @ w_attn + b_attn -> split bf16 q/k/v (q scaled)
    mma_gemm_qkv<<<dim3(C3_ / 128, M_ / 128), 256, G_SMEM_TOTAL>>>(
        aexp, b1exp, b_attn, KE_);

    // 2) flash attention -> writes y-split directly into g_aexp
    flash_kernel<<<dim3(T_ / 128, NH_, B_), 256, FL_SMEM_BYTES>>>();

    // 3) out = y @ w_proj + b_proj
    mma_gemm_bias<<<dim3(C_ / 128, M_ / 128), 256, G_SMEM_TOTAL>>>(
        aexp, b2exp, b_proj, out, M_, C_, KE_);
}